// round 13
// baseline (speedup 1.0000x reference)
#include <cuda_runtime.h>
#include <math.h>
#include <float.h>

#define N_NODES 20000
#define N_EDGES 320000
#define FDIM 40
#define TG 200          // T*F message dims
#define EMB 40
#define EPS_STD 1e-5f
#define EPS_GN 1e-5f
#define POST_NT 32
#define POST_BLOCKS (N_NODES / POST_NT)   // 625
#define FUSED_T 640
#define FUSED_W 20
#define SORT_W 96

// ------------------------- scratch (device globals) -------------------------
__device__ int   g_deg[N_NODES];
__device__ int   g_off[N_NODES + 1];
__device__ int   g_cur[N_NODES];
__device__ int   g_csr[N_EDGES];
__device__ float g_A[N_NODES * TG];        // x@Wpre_top + b_pre
__device__ float g_B[N_NODES * TG];        // x@Wpre_bot
__device__ float g_H[N_NODES * EMB];       // pre-norm hidden
__device__ float g_psum[POST_BLOCKS * EMB];
__device__ float g_psq[POST_BLOCKS * EMB];
__device__ float g_scale[EMB];
__device__ float g_bias2[EMB];

// ------------------------- CSR build -------------------------
__global__ void k_zero() {
    int i = blockIdx.x * blockDim.x + threadIdx.x;
    if (i < N_NODES) g_deg[i] = 0;
}

__global__ void k_count(const int* __restrict__ dst) {
    int e = blockIdx.x * blockDim.x + threadIdx.x;
    if (e < N_EDGES) atomicAdd(&g_deg[dst[e]], 1);
}

__global__ void k_scan() {
    __shared__ int sp[1024];
    int t = threadIdx.x;
    const int C = 20;  // 1024*20 = 20480 >= N
    int lo = t * C;
    int hi = lo + C; if (hi > N_NODES) hi = N_NODES;
    if (lo > N_NODES) lo = N_NODES;
    int s = 0;
    for (int i = lo; i < hi; i++) s += g_deg[i];
    sp[t] = s;
    __syncthreads();
    for (int o = 1; o < 1024; o <<= 1) {
        int v = (t >= o) ? sp[t - o] : 0;
        __syncthreads();
        sp[t] += v;
        __syncthreads();
    }
    int run = sp[t] - s;  // exclusive
    for (int i = lo; i < hi; i++) {
        g_off[i] = run; g_cur[i] = run;
        run += g_deg[i];
    }
    if (t == 1023) g_off[N_NODES] = sp[1023];
}

__global__ void k_fill(const int* __restrict__ src, const int* __restrict__ dst) {
    int e = blockIdx.x * blockDim.x + threadIdx.x;
    if (e < N_EDGES) {
        int p = atomicAdd(&g_cur[dst[e]], 1);
        g_csr[p] = src[e];
    }
}

// ------------------------- A/B precompute: [N,40] @ [40,400] -------------------------
__global__ void k_ab(const float* __restrict__ x, const float* __restrict__ Wpre,
                     const float* __restrict__ bpre) {
    __shared__ __align__(16) float xsT[FDIM * 64];  // [k][node]
    __shared__ __align__(16) float wsT[FDIM * 64];  // [k][col]
    int tid = threadIdx.x;
    int c0 = blockIdx.x * 64;  // 0..6 -> cols
    int n0 = blockIdx.y * 64;  // 0..312 -> nodes
    for (int idx = tid; idx < 64 * FDIM; idx += 256) {
        int nl = idx / FDIM, k = idx % FDIM;
        int n = n0 + nl;
        xsT[k * 64 + nl] = (n < N_NODES) ? x[n * FDIM + k] : 0.f;
    }
    for (int idx = tid; idx < 64 * FDIM; idx += 256) {
        int cl = idx / FDIM, k = idx % FDIM;
        int c = c0 + cl;
        float w = 0.f;
        if (c < 2 * TG) {
            if (c < TG) {
                int t = c / FDIM, g = c % FDIM;
                w = Wpre[t * 3200 + k * FDIM + g];
            } else {
                int cc = c - TG;
                int t = cc / FDIM, g = cc % FDIM;
                w = Wpre[t * 3200 + (FDIM + k) * FDIM + g];
            }
        }
        wsT[k * 64 + cl] = w;
    }
    __syncthreads();
    int tx = tid & 15, ty = tid >> 4;
    float acc[4][4];
#pragma unroll
    for (int i = 0; i < 4; i++)
#pragma unroll
        for (int j = 0; j < 4; j++) acc[i][j] = 0.f;
#pragma unroll 4
    for (int k = 0; k < FDIM; k++) {
        float4 xv = *reinterpret_cast<const float4*>(&xsT[k * 64 + ty * 4]);
        float4 wv = *reinterpret_cast<const float4*>(&wsT[k * 64 + tx * 4]);
        float xs[4] = {xv.x, xv.y, xv.z, xv.w};
        float ws[4] = {wv.x, wv.y, wv.z, wv.w};
#pragma unroll
        for (int i = 0; i < 4; i++)
#pragma unroll
            for (int j = 0; j < 4; j++) acc[i][j] = fmaf(xs[i], ws[j], acc[i][j]);
    }
#pragma unroll
    for (int i = 0; i < 4; i++) {
        int n = n0 + ty * 4 + i;
        if (n >= N_NODES) continue;
#pragma unroll
        for (int j = 0; j < 4; j++) {
            int c = c0 + tx * 4 + j;
            if (c >= 2 * TG) continue;
            float v = acc[i][j];
            if (c < TG) g_A[n * TG + c] = v + __ldg(&bpre[c]);
            else        g_B[n * TG + (c - TG)] = v;
        }
    }
}

// ------------------------- fused: sort -> aggregation -> post MLP -> W_lin -> norm partials -----
// smem float layout
#define SM_W    0
#define SM_IN   20800              // stride 801 per node
#define SM_X    (SM_IN + 32*801)   // 46432, stride 41
#define SM_S    (SM_X + 32*41)     // 47744
#define SM_Y    (SM_S + 64)        // 47808, stride 41
#define SM_WLIN (SM_Y + 32*41)     // 49120
#define SM_H    (SM_WLIN + 1600)   // 50720, stride 41
#define SM_SORT (SM_H + 32*41)     // 52032, 20 warps * 96 ints
#define SM_TOTAL (SM_SORT + FUSED_W*SORT_W)  // 53952 floats = 215808 B

__global__ void __launch_bounds__(FUSED_T, 1)
k_fused(const float* __restrict__ x, const float* __restrict__ Wpost,
        const float* __restrict__ bpost, const float* __restrict__ Wlin,
        const float* __restrict__ blin, const float* __restrict__ avgp) {
    extern __shared__ __align__(16) float sm[];
    float* w_sh  = sm + SM_W;
    float* in_sh = sm + SM_IN;
    float* x_sh  = sm + SM_X;
    float* s_sh  = sm + SM_S;
    float* y_sh  = sm + SM_Y;
    float* wlin  = sm + SM_WLIN;
    float* h_sh  = sm + SM_H;
    int*   sort_sh = reinterpret_cast<int*>(sm + SM_SORT);
    const int tid = threadIdx.x;          // 640
    const int n0 = blockIdx.x * POST_NT;

    // weight / x preloads (overlap with aggregation latency)
    for (int i = tid; i < 20800; i += FUSED_T) w_sh[i] = Wpost[i];
    for (int i = tid; i < 1600; i += FUSED_T) wlin[i] = Wlin[i];
    for (int i = tid; i < POST_NT * FDIM; i += FUSED_T) {
        int nl = i / FDIM, k = i % FDIM;
        x_sh[nl * 41 + k] = x[(n0 + nl) * FDIM + k];
    }

    const int w = tid >> 5, lane = tid & 31;
    const float avg = *avgp;
    const bool act1 = (lane < 18);        // lane+32 < 50 float4 slots

    // ---- Phase A: per-warp in-smem sort + aggregation, 20 warps over 32 nodes ----
    for (int nl = w; nl < POST_NT; nl += FUSED_W) {
        int n = n0 + nl;
        int beg = g_off[n], end = g_off[n + 1];
        int deg = end - beg;

        // canonical (sorted) neighbor order for determinism, in per-warp smem
        int* sb = sort_sh + w * SORT_W;
        bool small = (deg <= SORT_W);
        if (small) {
            for (int i = lane; i < deg; i += 32) sb[i] = __ldg(&g_csr[beg + i]);
            __syncwarp();
            for (int r = 0; r < deg; r++) {
                int start = r & 1;
                for (int i = start + 2 * lane; i + 1 < deg; i += 64) {
                    int a = sb[i], b = sb[i + 1];
                    if (a > b) { sb[i] = b; sb[i + 1] = a; }
                }
                __syncwarp();
            }
        }

        const float4* Ap = reinterpret_cast<const float4*>(g_A + (size_t)n * TG);
        float4 a0 = __ldg(&Ap[lane]);
        float4 a1 = make_float4(0.f, 0.f, 0.f, 0.f);
        if (act1) a1 = __ldg(&Ap[lane + 32]);

        float S[8], Q[8], S2[8], Q2[8], MN[8], MX[8];
#pragma unroll
        for (int u = 0; u < 8; u++) {
            S[u] = 0.f; Q[u] = 0.f; S2[u] = 0.f; Q2[u] = 0.f;
            MN[u] = FLT_MAX; MX[u] = -FLT_MAX;
        }

        int jj = 0;
        for (; jj + 1 < deg; jj += 2) {
            int s0 = small ? sb[jj]     : __ldg(&g_csr[beg + jj]);
            int s1 = small ? sb[jj + 1] : __ldg(&g_csr[beg + jj + 1]);
            const float4* Bp0 = reinterpret_cast<const float4*>(g_B + (size_t)s0 * TG);
            const float4* Bp1 = reinterpret_cast<const float4*>(g_B + (size_t)s1 * TG);
            float4 b0 = __ldg(&Bp0[lane]);
            float4 c0 = __ldg(&Bp1[lane]);
            {
                float v0 = a0.x + b0.x, v1 = a0.y + b0.y, v2 = a0.z + b0.z, v3 = a0.w + b0.w;
                S[0] += v0; Q[0] = fmaf(v0, v0, Q[0]); MN[0] = fminf(MN[0], v0); MX[0] = fmaxf(MX[0], v0);
                S[1] += v1; Q[1] = fmaf(v1, v1, Q[1]); MN[1] = fminf(MN[1], v1); MX[1] = fmaxf(MX[1], v1);
                S[2] += v2; Q[2] = fmaf(v2, v2, Q[2]); MN[2] = fminf(MN[2], v2); MX[2] = fmaxf(MX[2], v2);
                S[3] += v3; Q[3] = fmaf(v3, v3, Q[3]); MN[3] = fminf(MN[3], v3); MX[3] = fmaxf(MX[3], v3);
                float u0 = a0.x + c0.x, u1 = a0.y + c0.y, u2 = a0.z + c0.z, u3 = a0.w + c0.w;
                S2[0] += u0; Q2[0] = fmaf(u0, u0, Q2[0]); MN[0] = fminf(MN[0], u0); MX[0] = fmaxf(MX[0], u0);
                S2[1] += u1; Q2[1] = fmaf(u1, u1, Q2[1]); MN[1] = fminf(MN[1], u1); MX[1] = fmaxf(MX[1], u1);
                S2[2] += u2; Q2[2] = fmaf(u2, u2, Q2[2]); MN[2] = fminf(MN[2], u2); MX[2] = fmaxf(MX[2], u2);
                S2[3] += u3; Q2[3] = fmaf(u3, u3, Q2[3]); MN[3] = fminf(MN[3], u3); MX[3] = fmaxf(MX[3], u3);
            }
            if (act1) {
                float4 b1 = __ldg(&Bp0[lane + 32]);
                float4 c1 = __ldg(&Bp1[lane + 32]);
                float v0 = a1.x + b1.x, v1 = a1.y + b1.y, v2 = a1.z + b1.z, v3 = a1.w + b1.w;
                S[4] += v0; Q[4] = fmaf(v0, v0, Q[4]); MN[4] = fminf(MN[4], v0); MX[4] = fmaxf(MX[4], v0);
                S[5] += v1; Q[5] = fmaf(v1, v1, Q[5]); MN[5] = fminf(MN[5], v1); MX[5] = fmaxf(MX[5], v1);
                S[6] += v2; Q[6] = fmaf(v2, v2, Q[6]); MN[6] = fminf(MN[6], v2); MX[6] = fmaxf(MX[6], v2);
                S[7] += v3; Q[7] = fmaf(v3, v3, Q[7]); MN[7] = fminf(MN[7], v3); MX[7] = fmaxf(MX[7], v3);
                float u0 = a1.x + c1.x, u1 = a1.y + c1.y, u2 = a1.z + c1.z, u3 = a1.w + c1.w;
                S2[4] += u0; Q2[4] = fmaf(u0, u0, Q2[4]); MN[4] = fminf(MN[4], u0); MX[4] = fmaxf(MX[4], u0);
                S2[5] += u1; Q2[5] = fmaf(u1, u1, Q2[5]); MN[5] = fminf(MN[5], u1); MX[5] = fmaxf(MX[5], u1);
                S2[6] += u2; Q2[6] = fmaf(u2, u2, Q2[6]); MN[6] = fminf(MN[6], u2); MX[6] = fmaxf(MX[6], u2);
                S2[7] += u3; Q2[7] = fmaf(u3, u3, Q2[7]); MN[7] = fminf(MN[7], u3); MX[7] = fmaxf(MX[7], u3);
            }
        }
        if (jj < deg) {
            int s0 = small ? sb[jj] : __ldg(&g_csr[beg + jj]);
            const float4* Bp0 = reinterpret_cast<const float4*>(g_B + (size_t)s0 * TG);
            float4 b0 = __ldg(&Bp0[lane]);
            float v0 = a0.x + b0.x, v1 = a0.y + b0.y, v2 = a0.z + b0.z, v3 = a0.w + b0.w;
            S[0] += v0; Q[0] = fmaf(v0, v0, Q[0]); MN[0] = fminf(MN[0], v0); MX[0] = fmaxf(MX[0], v0);
            S[1] += v1; Q[1] = fmaf(v1, v1, Q[1]); MN[1] = fminf(MN[1], v1); MX[1] = fmaxf(MX[1], v1);
            S[2] += v2; Q[2] = fmaf(v2, v2, Q[2]); MN[2] = fminf(MN[2], v2); MX[2] = fmaxf(MX[2], v2);
            S[3] += v3; Q[3] = fmaf(v3, v3, Q[3]); MN[3] = fminf(MN[3], v3); MX[3] = fmaxf(MX[3], v3);
            if (act1) {
                float4 b1 = __ldg(&Bp0[lane + 32]);
                float u0 = a1.x + b1.x, u1 = a1.y + b1.y, u2 = a1.z + b1.z, u3 = a1.w + b1.w;
                S[4] += u0; Q[4] = fmaf(u0, u0, Q[4]); MN[4] = fminf(MN[4], u0); MX[4] = fmaxf(MX[4], u0);
                S[5] += u1; Q[5] = fmaf(u1, u1, Q[5]); MN[5] = fminf(MN[5], u1); MX[5] = fmaxf(MX[5], u1);
                S[6] += u2; Q[6] = fmaf(u2, u2, Q[6]); MN[6] = fminf(MN[6], u2); MX[6] = fmaxf(MX[6], u2);
                S[7] += u3; Q[7] = fmaf(u3, u3, Q[7]); MN[7] = fminf(MN[7], u3); MX[7] = fmaxf(MX[7], u3);
            }
        }
#pragma unroll
        for (int u = 0; u < 8; u++) { S[u] += S2[u]; Q[u] += Q2[u]; }

        float denom = (float)(deg > 1 ? deg : 1);
        float inv = 1.f / denom;
        float* row = in_sh + nl * 801;
#pragma unroll
        for (int u = 0; u < 8; u++) {
            int d = (u < 4) ? (4 * lane + u) : (4 * lane + 124 + u);  // 4*(lane+32)+(u-4)
            if (d < TG) {
                float mean = S[u] * inv;
                float var = Q[u] * inv - mean * mean;
                float stdv = sqrtf(fmaxf(var, 0.f) + EPS_STD);
                float mnv = (deg > 0) ? MN[u] : 0.f;
                float mxv = (deg > 0) ? MX[u] : 0.f;
                int t = d / FDIM, f = d - t * FDIM;
                float* o = row + t * 160 + f;
                o[0] = mean; o[40] = mnv; o[80] = mxv; o[120] = stdv;
            }
        }
        if (lane == 0) {
            float logd = logf(denom + 1.f);
            s_sh[nl * 2] = logd / avg;
            s_sh[nl * 2 + 1] = avg / logd;
        }
    }
    __syncthreads();

    // ---- Phase B: per-(tower, out-pair, node) GEMM, scaler-folded, smem weights ----
    {
        const int t = w >> 2;       // 0..4
        const int gp = w & 3;       // 0..3 -> outputs 2*gp, 2*gp+1
        const int nl = lane;
        const float* wt = w_sh + t * 4160 + gp * 2;
        float ax0 = 0.f, ax1 = 0.f;
        float a10 = 0.f, a11 = 0.f, a20 = 0.f, a21 = 0.f, a30 = 0.f, a31 = 0.f;
        const float* xr = x_sh + nl * 41;
#pragma unroll 4
        for (int k = 0; k < FDIM; k++) {
            float v = xr[k];
            float2 wv = *reinterpret_cast<const float2*>(wt + k * 8);
            ax0 = fmaf(v, wv.x, ax0); ax1 = fmaf(v, wv.y, ax1);
        }
        const float* ar = in_sh + nl * 801 + t * 160;
#pragma unroll 4
        for (int k = 0; k < 160; k++) {
            float v = ar[k];
            float2 w1 = *reinterpret_cast<const float2*>(wt + (40 + k) * 8);
            float2 w2 = *reinterpret_cast<const float2*>(wt + (200 + k) * 8);
            float2 w3 = *reinterpret_cast<const float2*>(wt + (360 + k) * 8);
            a10 = fmaf(v, w1.x, a10); a11 = fmaf(v, w1.y, a11);
            a20 = fmaf(v, w2.x, a20); a21 = fmaf(v, w2.y, a21);
            a30 = fmaf(v, w3.x, a30); a31 = fmaf(v, w3.y, a31);
        }
        float s1 = s_sh[nl * 2], s2 = s_sh[nl * 2 + 1];
        float y0 = ax0 + a10 + s1 * a20 + s2 * a30 + __ldg(&bpost[t * 8 + gp * 2]);
        float y1 = ax1 + a11 + s1 * a21 + s2 * a31 + __ldg(&bpost[t * 8 + gp * 2 + 1]);
        y_sh[nl * 41 + t * 8 + gp * 2]     = y0;
        y_sh[nl * 41 + t * 8 + gp * 2 + 1] = y1;
    }
    __syncthreads();

    // ---- W_lin: 32 nodes x 40 outs = 1280 tasks ----
    for (int r = 0; r < 2; r++) {
        int task = tid + r * FUSED_T;
        int nl = task / EMB, j = task % EMB;
        float acc = __ldg(&blin[j]);
        const float* yr = y_sh + nl * 41;
#pragma unroll 4
        for (int o = 0; o < EMB; o++) acc = fmaf(yr[o], wlin[o * EMB + j], acc);
        h_sh[nl * 41 + j] = acc;
        g_H[(size_t)(n0 + nl) * EMB + j] = acc;
    }
    __syncthreads();

    // ---- GraphNorm partials ----
    if (tid < EMB) {
        float s = 0.f, q = 0.f;
        for (int nl = 0; nl < POST_NT; nl++) {
            float v = h_sh[nl * 41 + tid];
            s += v;
            q = fmaf(v, v, q);
        }
        g_psum[blockIdx.x * EMB + tid] = s;
        g_psq[blockIdx.x * EMB + tid] = q;
    }
}

// ------------------------- GraphNorm finalize (parallel, fixed tree) -------------------------
__global__ void k_norm(const float* __restrict__ gnw, const float* __restrict__ gnb,
                       const float* __restrict__ gms) {
    __shared__ float sbuf[256], qbuf[256];
    int j = blockIdx.x;          // 40 blocks, one per channel
    int t = threadIdx.x;         // 256
    float s = 0.f, q = 0.f;
    for (int b = t; b < POST_BLOCKS; b += 256) {
        s += g_psum[b * EMB + j];
        q += g_psq[b * EMB + j];
    }
    sbuf[t] = s; qbuf[t] = q;
    __syncthreads();
    for (int o = 128; o > 0; o >>= 1) {
        if (t < o) { sbuf[t] += sbuf[t + o]; qbuf[t] += qbuf[t + o]; }
        __syncthreads();
    }
    if (t == 0) {
        float mu  = sbuf[0] / (float)N_NODES;
        float msq = qbuf[0] / (float)N_NODES;
        float ms  = gms[j];
        float var = msq - 2.f * ms * mu * mu + ms * ms * mu * mu;
        float scale = gnw[j] * rsqrtf(var + EPS_GN);
        g_scale[j] = scale;
        g_bias2[j] = gnb[j] - scale * ms * mu;
    }
}

// ------------------------- head: relu(norm) -> relu(@W1+b1) -> @W2+b2 -------------------------
__global__ void k_head(const float* __restrict__ W1, const float* __restrict__ b1,
                       const float* __restrict__ W2, const float* __restrict__ b2,
                       float* __restrict__ out) {
    __shared__ float w1s[1600], w2s[80], b1s[40], b2s[2], scs[40], bss[40];
    __shared__ float gsh[8][40], zsh[8][40];
    int tid = threadIdx.x;
    for (int idx = tid; idx < 1600; idx += 256) w1s[idx] = W1[idx];
    if (tid < 80) w2s[tid] = W2[tid];
    if (tid < 40) { b1s[tid] = b1[tid]; scs[tid] = g_scale[tid]; bss[tid] = g_bias2[tid]; }
    if (tid < 2)  b2s[tid] = b2[tid];
    __syncthreads();

    int w = tid >> 5, lane = tid & 31;
    int n = blockIdx.x * 8 + w;
    if (n >= N_NODES) return;

    for (int j = lane; j < EMB; j += 32) {
        float hv = g_H[(size_t)n * EMB + j];
        gsh[w][j] = fmaxf(scs[j] * hv + bss[j], 0.f);
    }
    __syncwarp();
    for (int j = lane; j < EMB; j += 32) {
        float acc = b1s[j];
#pragma unroll 4
        for (int f = 0; f < EMB; f++) acc = fmaf(gsh[w][f], w1s[f * EMB + j], acc);
        zsh[w][j] = fmaxf(acc, 0.f);
    }
    __syncwarp();
    if (lane < 2) {
        float acc = b2s[lane];
#pragma unroll 4
        for (int f = 0; f < EMB; f++) acc = fmaf(zsh[w][f], w2s[f * 2 + lane], acc);
        out[(size_t)n * 2 + lane] = acc;
    }
}

// ------------------------- launch -------------------------
extern "C" void kernel_launch(void* const* d_in, const int* in_sizes, int n_in,
                              void* d_out, int out_size) {
    const float* x     = (const float*)d_in[0];
    const int*   ei    = (const int*)d_in[1];
    const float* Wpre  = (const float*)d_in[2];
    const float* bpre  = (const float*)d_in[3];
    const float* Wpost = (const float*)d_in[4];
    const float* bpost = (const float*)d_in[5];
    const float* Wlin  = (const float*)d_in[6];
    const float* blin  = (const float*)d_in[7];
    const float* gnw   = (const float*)d_in[8];
    const float* gnb   = (const float*)d_in[9];
    const float* gms   = (const float*)d_in[10];
    const float* W1    = (const float*)d_in[11];
    const float* b1    = (const float*)d_in[12];
    const float* W2    = (const float*)d_in[13];
    const float* b2    = (const float*)d_in[14];
    const float* avg   = (const float*)d_in[15];
    const int* src = ei;
    const int* dst = ei + N_EDGES;
    float* out = (float*)d_out;

    const size_t fused_smem = (size_t)SM_TOTAL * sizeof(float);
    cudaFuncSetAttribute(k_fused, cudaFuncAttributeMaxDynamicSharedMemorySize, (int)fused_smem);

    k_zero<<<(N_NODES + 255) / 256, 256>>>();
    k_count<<<(N_EDGES + 255) / 256, 256>>>(dst);
    k_scan<<<1, 1024>>>();
    k_fill<<<(N_EDGES + 255) / 256, 256>>>(src, dst);
    dim3 abg(7, 313);
    k_ab<<<abg, 256>>>(x, Wpre, bpre);
    k_fused<<<POST_BLOCKS, FUSED_T, fused_smem>>>(x, Wpost, bpost, Wlin, blin, avg);
    k_norm<<<EMB, 256>>>(gnw, gnb, gms);
    k_head<<<(N_NODES + 7) / 8, 256>>>(W1, b1, W2, b2, out);
}

// round 14
// speedup vs baseline: 1.0242x; 1.0242x over previous
#include <cuda_runtime.h>
#include <math.h>
#include <float.h>

#define N_NODES 20000
#define N_EDGES 320000
#define FDIM 40
#define TG 200          // T*F message dims
#define EMB 40
#define EPS_STD 1e-5f
#define EPS_GN 1e-5f
#define POST_NT 32
#define POST_BLOCKS (N_NODES / POST_NT)   // 625
#define SORT_CAP 128
#define FUSED_T 640
#define FUSED_W 20

// packed f32x2 helpers (bit-identical to two scalar fmaf's)
#define FFMA2(acc, a, b) \
    asm("fma.rn.f32x2 %0, %1, %2, %3;" : "=l"(acc) : "l"(a), "l"(b), "l"(acc))
#define PACK2(out, lo, hi) \
    asm("mov.b64 %0, {%1, %2};" : "=l"(out) : "r"(lo), "r"(hi))
#define UNPACK2(lo, hi, in) \
    asm("mov.b64 {%0, %1}, %2;" : "=r"(lo), "=r"(hi) : "l"(in))

// ------------------------- scratch (device globals) -------------------------
__device__ int   g_deg[N_NODES];
__device__ int   g_off[N_NODES + 1];
__device__ int   g_cur[N_NODES];
__device__ int   g_csr[N_EDGES];
__device__ float g_A[N_NODES * TG];        // x@Wpre_top + b_pre
__device__ float g_B[N_NODES * TG];        // x@Wpre_bot
__device__ float g_H[N_NODES * EMB];       // pre-norm hidden
__device__ float g_psum[POST_BLOCKS * EMB];
__device__ float g_psq[POST_BLOCKS * EMB];
__device__ float g_scale[EMB];
__device__ float g_bias2[EMB];

// ------------------------- CSR build -------------------------
__global__ void k_zero() {
    int i = blockIdx.x * blockDim.x + threadIdx.x;
    if (i < N_NODES) g_deg[i] = 0;
}

__global__ void k_count(const int* __restrict__ dst) {
    int e = blockIdx.x * blockDim.x + threadIdx.x;
    if (e < N_EDGES) atomicAdd(&g_deg[dst[e]], 1);
}

__global__ void k_scan() {
    __shared__ int sp[1024];
    int t = threadIdx.x;
    const int C = 20;  // 1024*20 = 20480 >= N
    int lo = t * C;
    int hi = lo + C; if (hi > N_NODES) hi = N_NODES;
    if (lo > N_NODES) lo = N_NODES;
    int s = 0;
    for (int i = lo; i < hi; i++) s += g_deg[i];
    sp[t] = s;
    __syncthreads();
    for (int o = 1; o < 1024; o <<= 1) {
        int v = (t >= o) ? sp[t - o] : 0;
        __syncthreads();
        sp[t] += v;
        __syncthreads();
    }
    int run = sp[t] - s;  // exclusive
    for (int i = lo; i < hi; i++) {
        g_off[i] = run; g_cur[i] = run;
        run += g_deg[i];
    }
    if (t == 1023) g_off[N_NODES] = sp[1023];
}

__global__ void k_fill(const int* __restrict__ src, const int* __restrict__ dst) {
    int e = blockIdx.x * blockDim.x + threadIdx.x;
    if (e < N_EDGES) {
        int p = atomicAdd(&g_cur[dst[e]], 1);
        g_csr[p] = src[e];
    }
}

// deterministic order: sort each node's neighbor list
__global__ void k_sort() {
    __shared__ int buf[8][SORT_CAP];
    int w = threadIdx.x >> 5, lane = threadIdx.x & 31;
    int n = blockIdx.x * 8 + w;
    if (n >= N_NODES) return;
    int beg = g_off[n];
    int deg = g_off[n + 1] - beg;
    if (deg <= 1 || deg > SORT_CAP) return;
    for (int i = lane; i < deg; i += 32) buf[w][i] = g_csr[beg + i];
    __syncwarp();
    for (int r = 0; r < deg; r++) {
        int start = r & 1;
        for (int i = start + 2 * lane; i + 1 < deg; i += 64) {
            int a = buf[w][i], b = buf[w][i + 1];
            if (a > b) { buf[w][i] = b; buf[w][i + 1] = a; }
        }
        __syncwarp();
    }
    for (int i = lane; i < deg; i += 32) g_csr[beg + i] = buf[w][i];
}

// ------------------------- A/B precompute: [N,40] @ [40,400] -------------------------
__global__ void k_ab(const float* __restrict__ x, const float* __restrict__ Wpre,
                     const float* __restrict__ bpre) {
    __shared__ __align__(16) float xsT[FDIM * 64];  // [k][node]
    __shared__ __align__(16) float wsT[FDIM * 64];  // [k][col]
    int tid = threadIdx.x;
    int c0 = blockIdx.x * 64;  // 0..6 -> cols
    int n0 = blockIdx.y * 64;  // 0..312 -> nodes
    for (int idx = tid; idx < 64 * FDIM; idx += 256) {
        int nl = idx / FDIM, k = idx % FDIM;
        int n = n0 + nl;
        xsT[k * 64 + nl] = (n < N_NODES) ? x[n * FDIM + k] : 0.f;
    }
    for (int idx = tid; idx < 64 * FDIM; idx += 256) {
        int cl = idx / FDIM, k = idx % FDIM;
        int c = c0 + cl;
        float w = 0.f;
        if (c < 2 * TG) {
            if (c < TG) {
                int t = c / FDIM, g = c % FDIM;
                w = Wpre[t * 3200 + k * FDIM + g];
            } else {
                int cc = c - TG;
                int t = cc / FDIM, g = cc % FDIM;
                w = Wpre[t * 3200 + (FDIM + k) * FDIM + g];
            }
        }
        wsT[k * 64 + cl] = w;
    }
    __syncthreads();
    int tx = tid & 15, ty = tid >> 4;
    float acc[4][4];
#pragma unroll
    for (int i = 0; i < 4; i++)
#pragma unroll
        for (int j = 0; j < 4; j++) acc[i][j] = 0.f;
#pragma unroll 4
    for (int k = 0; k < FDIM; k++) {
        float4 xv = *reinterpret_cast<const float4*>(&xsT[k * 64 + ty * 4]);
        float4 wv = *reinterpret_cast<const float4*>(&wsT[k * 64 + tx * 4]);
        float xs[4] = {xv.x, xv.y, xv.z, xv.w};
        float ws[4] = {wv.x, wv.y, wv.z, wv.w};
#pragma unroll
        for (int i = 0; i < 4; i++)
#pragma unroll
            for (int j = 0; j < 4; j++) acc[i][j] = fmaf(xs[i], ws[j], acc[i][j]);
    }
#pragma unroll
    for (int i = 0; i < 4; i++) {
        int n = n0 + ty * 4 + i;
        if (n >= N_NODES) continue;
#pragma unroll
        for (int j = 0; j < 4; j++) {
            int c = c0 + tx * 4 + j;
            if (c >= 2 * TG) continue;
            float v = acc[i][j];
            if (c < TG) g_A[n * TG + c] = v + __ldg(&bpre[c]);
            else        g_B[n * TG + (c - TG)] = v;
        }
    }
}

// ------------------------- fused: aggregation -> post MLP -> W_lin -> norm partials -----
// smem float layout
#define SM_W    0
#define SM_IN   20800              // stride 801 per node
#define SM_X    (SM_IN + 32*801)   // 46432, stride 41
#define SM_S    (SM_X + 32*41)     // 47744
#define SM_Y    (SM_S + 64)        // 47808, stride 41
#define SM_WLIN (SM_Y + 32*41)     // 49120
#define SM_H    (SM_WLIN + 1600)   // 50720, stride 41
#define SM_TOTAL (SM_H + 32*41)    // 52032 floats = 208128 B

__global__ void __launch_bounds__(FUSED_T, 1)
k_fused(const float* __restrict__ x, const float* __restrict__ Wpost,
        const float* __restrict__ bpost, const float* __restrict__ Wlin,
        const float* __restrict__ blin, const float* __restrict__ avgp) {
    extern __shared__ __align__(16) float sm[];
    float* w_sh  = sm + SM_W;
    float* in_sh = sm + SM_IN;
    float* x_sh  = sm + SM_X;
    float* s_sh  = sm + SM_S;
    float* y_sh  = sm + SM_Y;
    float* wlin  = sm + SM_WLIN;
    float* h_sh  = sm + SM_H;
    const int tid = threadIdx.x;          // 640
    const int n0 = blockIdx.x * POST_NT;

    // weight / x preloads (overlap with aggregation latency)
    for (int i = tid; i < 20800; i += FUSED_T) w_sh[i] = Wpost[i];
    for (int i = tid; i < 1600; i += FUSED_T) wlin[i] = Wlin[i];
    for (int i = tid; i < POST_NT * FDIM; i += FUSED_T) {
        int nl = i / FDIM, k = i % FDIM;
        x_sh[nl * 41 + k] = x[(n0 + nl) * FDIM + k];
    }

    const int w = tid >> 5, lane = tid & 31;
    const float avg = *avgp;
    const bool act1 = (lane < 18);        // lane+32 < 50 float4 slots

    // ---- Phase A: aggregation, 20 warps round-robin over 32 nodes ----
    for (int nl = w; nl < POST_NT; nl += FUSED_W) {
        int n = n0 + nl;
        int beg = g_off[n], end = g_off[n + 1];
        int deg = end - beg;
        const float4* Ap = reinterpret_cast<const float4*>(g_A + (size_t)n * TG);
        float4 a0 = __ldg(&Ap[lane]);
        float4 a1 = make_float4(0.f, 0.f, 0.f, 0.f);
        if (act1) a1 = __ldg(&Ap[lane + 32]);

        float S[8], Q[8], S2[8], Q2[8], MN[8], MX[8];
#pragma unroll
        for (int u = 0; u < 8; u++) {
            S[u] = 0.f; Q[u] = 0.f; S2[u] = 0.f; Q2[u] = 0.f;
            MN[u] = FLT_MAX; MX[u] = -FLT_MAX;
        }

        // warp-cooperative index fetch: one coalesced LDG per 32-edge chunk,
        // indices broadcast via shfl -> B-row gathers are the only loads in the loop
        for (int base = beg; base < end; base += 32) {
            int rem = end - base;
            int cnt = rem < 32 ? rem : 32;
            int myidx = 0;
            if (lane < cnt) myidx = __ldg(&g_csr[base + lane]);
            int jj = 0;
            for (; jj + 1 < cnt; jj += 2) {
                int s0 = __shfl_sync(0xffffffffu, myidx, jj);
                int s1 = __shfl_sync(0xffffffffu, myidx, jj + 1);
                const float4* Bp0 = reinterpret_cast<const float4*>(g_B + (size_t)s0 * TG);
                const float4* Bp1 = reinterpret_cast<const float4*>(g_B + (size_t)s1 * TG);
                float4 b0 = __ldg(&Bp0[lane]);
                float4 c0 = __ldg(&Bp1[lane]);
                {
                    float v0 = a0.x + b0.x, v1 = a0.y + b0.y, v2 = a0.z + b0.z, v3 = a0.w + b0.w;
                    S[0] += v0; Q[0] = fmaf(v0, v0, Q[0]); MN[0] = fminf(MN[0], v0); MX[0] = fmaxf(MX[0], v0);
                    S[1] += v1; Q[1] = fmaf(v1, v1, Q[1]); MN[1] = fminf(MN[1], v1); MX[1] = fmaxf(MX[1], v1);
                    S[2] += v2; Q[2] = fmaf(v2, v2, Q[2]); MN[2] = fminf(MN[2], v2); MX[2] = fmaxf(MX[2], v2);
                    S[3] += v3; Q[3] = fmaf(v3, v3, Q[3]); MN[3] = fminf(MN[3], v3); MX[3] = fmaxf(MX[3], v3);
                    float u0 = a0.x + c0.x, u1 = a0.y + c0.y, u2 = a0.z + c0.z, u3 = a0.w + c0.w;
                    S2[0] += u0; Q2[0] = fmaf(u0, u0, Q2[0]); MN[0] = fminf(MN[0], u0); MX[0] = fmaxf(MX[0], u0);
                    S2[1] += u1; Q2[1] = fmaf(u1, u1, Q2[1]); MN[1] = fminf(MN[1], u1); MX[1] = fmaxf(MX[1], u1);
                    S2[2] += u2; Q2[2] = fmaf(u2, u2, Q2[2]); MN[2] = fminf(MN[2], u2); MX[2] = fmaxf(MX[2], u2);
                    S2[3] += u3; Q2[3] = fmaf(u3, u3, Q2[3]); MN[3] = fminf(MN[3], u3); MX[3] = fmaxf(MX[3], u3);
                }
                if (act1) {
                    float4 b1 = __ldg(&Bp0[lane + 32]);
                    float4 c1 = __ldg(&Bp1[lane + 32]);
                    float v0 = a1.x + b1.x, v1 = a1.y + b1.y, v2 = a1.z + b1.z, v3 = a1.w + b1.w;
                    S[4] += v0; Q[4] = fmaf(v0, v0, Q[4]); MN[4] = fminf(MN[4], v0); MX[4] = fmaxf(MX[4], v0);
                    S[5] += v1; Q[5] = fmaf(v1, v1, Q[5]); MN[5] = fminf(MN[5], v1); MX[5] = fmaxf(MX[5], v1);
                    S[6] += v2; Q[6] = fmaf(v2, v2, Q[6]); MN[6] = fminf(MN[6], v2); MX[6] = fmaxf(MX[6], v2);
                    S[7] += v3; Q[7] = fmaf(v3, v3, Q[7]); MN[7] = fminf(MN[7], v3); MX[7] = fmaxf(MX[7], v3);
                    float u0 = a1.x + c1.x, u1 = a1.y + c1.y, u2 = a1.z + c1.z, u3 = a1.w + c1.w;
                    S2[4] += u0; Q2[4] = fmaf(u0, u0, Q2[4]); MN[4] = fminf(MN[4], u0); MX[4] = fmaxf(MX[4], u0);
                    S2[5] += u1; Q2[5] = fmaf(u1, u1, Q2[5]); MN[5] = fminf(MN[5], u1); MX[5] = fmaxf(MX[5], u1);
                    S2[6] += u2; Q2[6] = fmaf(u2, u2, Q2[6]); MN[6] = fminf(MN[6], u2); MX[6] = fmaxf(MX[6], u2);
                    S2[7] += u3; Q2[7] = fmaf(u3, u3, Q2[7]); MN[7] = fminf(MN[7], u3); MX[7] = fmaxf(MX[7], u3);
                }
            }
            if (jj < cnt) {
                int s0 = __shfl_sync(0xffffffffu, myidx, jj);
                const float4* Bp0 = reinterpret_cast<const float4*>(g_B + (size_t)s0 * TG);
                float4 b0 = __ldg(&Bp0[lane]);
                float v0 = a0.x + b0.x, v1 = a0.y + b0.y, v2 = a0.z + b0.z, v3 = a0.w + b0.w;
                S[0] += v0; Q[0] = fmaf(v0, v0, Q[0]); MN[0] = fminf(MN[0], v0); MX[0] = fmaxf(MX[0], v0);
                S[1] += v1; Q[1] = fmaf(v1, v1, Q[1]); MN[1] = fminf(MN[1], v1); MX[1] = fmaxf(MX[1], v1);
                S[2] += v2; Q[2] = fmaf(v2, v2, Q[2]); MN[2] = fminf(MN[2], v2); MX[2] = fmaxf(MX[2], v2);
                S[3] += v3; Q[3] = fmaf(v3, v3, Q[3]); MN[3] = fminf(MN[3], v3); MX[3] = fmaxf(MX[3], v3);
                if (act1) {
                    float4 b1 = __ldg(&Bp0[lane + 32]);
                    float u0 = a1.x + b1.x, u1 = a1.y + b1.y, u2 = a1.z + b1.z, u3 = a1.w + b1.w;
                    S[4] += u0; Q[4] = fmaf(u0, u0, Q[4]); MN[4] = fminf(MN[4], u0); MX[4] = fmaxf(MX[4], u0);
                    S[5] += u1; Q[5] = fmaf(u1, u1, Q[5]); MN[5] = fminf(MN[5], u1); MX[5] = fmaxf(MX[5], u1);
                    S[6] += u2; Q[6] = fmaf(u2, u2, Q[6]); MN[6] = fminf(MN[6], u2); MX[6] = fmaxf(MX[6], u2);
                    S[7] += u3; Q[7] = fmaf(u3, u3, Q[7]); MN[7] = fminf(MN[7], u3); MX[7] = fmaxf(MX[7], u3);
                }
            }
        }
#pragma unroll
        for (int u = 0; u < 8; u++) { S[u] += S2[u]; Q[u] += Q2[u]; }

        float denom = (float)(deg > 1 ? deg : 1);
        float inv = 1.f / denom;
        float* row = in_sh + nl * 801;
#pragma unroll
        for (int u = 0; u < 8; u++) {
            int d = (u < 4) ? (4 * lane + u) : (4 * lane + 124 + u);  // 4*(lane+32)+(u-4)
            if (d < TG) {
                float mean = S[u] * inv;
                float var = Q[u] * inv - mean * mean;
                float stdv = sqrtf(fmaxf(var, 0.f) + EPS_STD);
                float mnv = (deg > 0) ? MN[u] : 0.f;
                float mxv = (deg > 0) ? MX[u] : 0.f;
                int t = d / FDIM, f = d - t * FDIM;
                float* o = row + t * 160 + f;
                o[0] = mean; o[40] = mnv; o[80] = mxv; o[120] = stdv;
            }
        }
        if (lane == 0) {
            float logd = logf(denom + 1.f);
            s_sh[nl * 2] = logd / avg;
            s_sh[nl * 2 + 1] = avg / logd;
        }
    }
    __syncthreads();

    // ---- Phase B: per-(tower, out-pair, node) GEMM, f32x2-packed, smem weights ----
    {
        const int t = w >> 2;       // 0..4
        const int gp = w & 3;       // 0..3 -> outputs 2*gp, 2*gp+1
        const int nl = lane;
        const float* wt = w_sh + t * 4160 + gp * 2;   // 8-byte aligned
        unsigned long long accx = 0ull, acc1 = 0ull, acc2 = 0ull, acc3 = 0ull;
        const float* xr = x_sh + nl * 41;
#pragma unroll 4
        for (int k = 0; k < FDIM; k++) {
            float v = xr[k];
            unsigned long long vv;
            PACK2(vv, __float_as_uint(v), __float_as_uint(v));
            unsigned long long wv = *reinterpret_cast<const unsigned long long*>(wt + k * 8);
            FFMA2(accx, vv, wv);
        }
        const float* ar = in_sh + nl * 801 + t * 160;
#pragma unroll 4
        for (int k = 0; k < 160; k++) {
            float v = ar[k];
            unsigned long long vv;
            PACK2(vv, __float_as_uint(v), __float_as_uint(v));
            unsigned long long w1 = *reinterpret_cast<const unsigned long long*>(wt + (40 + k) * 8);
            unsigned long long w2 = *reinterpret_cast<const unsigned long long*>(wt + (200 + k) * 8);
            unsigned long long w3 = *reinterpret_cast<const unsigned long long*>(wt + (360 + k) * 8);
            FFMA2(acc1, vv, w1);
            FFMA2(acc2, vv, w2);
            FFMA2(acc3, vv, w3);
        }
        unsigned int x0i, x1i, a10i, a11i, a20i, a21i, a30i, a31i;
        UNPACK2(x0i, x1i, accx);
        UNPACK2(a10i, a11i, acc1);
        UNPACK2(a20i, a21i, acc2);
        UNPACK2(a30i, a31i, acc3);
        float ax0 = __uint_as_float(x0i),  ax1 = __uint_as_float(x1i);
        float a10 = __uint_as_float(a10i), a11 = __uint_as_float(a11i);
        float a20 = __uint_as_float(a20i), a21 = __uint_as_float(a21i);
        float a30 = __uint_as_float(a30i), a31 = __uint_as_float(a31i);
        float s1 = s_sh[nl * 2], s2 = s_sh[nl * 2 + 1];
        float y0 = ax0 + a10 + s1 * a20 + s2 * a30 + __ldg(&bpost[t * 8 + gp * 2]);
        float y1 = ax1 + a11 + s1 * a21 + s2 * a31 + __ldg(&bpost[t * 8 + gp * 2 + 1]);
        y_sh[nl * 41 + t * 8 + gp * 2]     = y0;
        y_sh[nl * 41 + t * 8 + gp * 2 + 1] = y1;
    }
    __syncthreads();

    // ---- W_lin: 32 nodes x 40 outs = 1280 tasks ----
    for (int r = 0; r < 2; r++) {
        int task = tid + r * FUSED_T;
        int nl = task / EMB, j = task % EMB;
        float acc = __ldg(&blin[j]);
        const float* yr = y_sh + nl * 41;
#pragma unroll 4
        for (int o = 0; o < EMB; o++) acc = fmaf(yr[o], wlin[o * EMB + j], acc);
        h_sh[nl * 41 + j] = acc;
        g_H[(size_t)(n0 + nl) * EMB + j] = acc;
    }
    __syncthreads();

    // ---- GraphNorm partials ----
    if (tid < EMB) {
        float s = 0.f, q = 0.f;
        for (int nl = 0; nl < POST_NT; nl++) {
            float v = h_sh[nl * 41 + tid];
            s += v;
            q = fmaf(v, v, q);
        }
        g_psum[blockIdx.x * EMB + tid] = s;
        g_psq[blockIdx.x * EMB + tid] = q;
    }
}

// ------------------------- GraphNorm finalize (parallel, fixed tree) -------------------------
__global__ void k_norm(const float* __restrict__ gnw, const float* __restrict__ gnb,
                       const float* __restrict__ gms) {
    __shared__ float sbuf[256], qbuf[256];
    int j = blockIdx.x;          // 40 blocks, one per channel
    int t = threadIdx.x;         // 256
    float s = 0.f, q = 0.f;
    for (int b = t; b < POST_BLOCKS; b += 256) {
        s += g_psum[b * EMB + j];
        q += g_psq[b * EMB + j];
    }
    sbuf[t] = s; qbuf[t] = q;
    __syncthreads();
    for (int o = 128; o > 0; o >>= 1) {
        if (t < o) { sbuf[t] += sbuf[t + o]; qbuf[t] += qbuf[t + o]; }
        __syncthreads();
    }
    if (t == 0) {
        float mu  = sbuf[0] / (float)N_NODES;
        float msq = qbuf[0] / (float)N_NODES;
        float ms  = gms[j];
        float var = msq - 2.f * ms * mu * mu + ms * ms * mu * mu;
        float scale = gnw[j] * rsqrtf(var + EPS_GN);
        g_scale[j] = scale;
        g_bias2[j] = gnb[j] - scale * ms * mu;
    }
}

// ------------------------- head: relu(norm) -> relu(@W1+b1) -> @W2+b2 -------------------------
__global__ void k_head(const float* __restrict__ W1, const float* __restrict__ b1,
                       const float* __restrict__ W2, const float* __restrict__ b2,
                       float* __restrict__ out) {
    __shared__ float w1s[1600], w2s[80], b1s[40], b2s[2], scs[40], bss[40];
    __shared__ float gsh[8][40], zsh[8][40];
    int tid = threadIdx.x;
    for (int idx = tid; idx < 1600; idx += 256) w1s[idx] = W1[idx];
    if (tid < 80) w2s[tid] = W2[tid];
    if (tid < 40) { b1s[tid] = b1[tid]; scs[tid] = g_scale[tid]; bss[tid] = g_bias2[tid]; }
    if (tid < 2)  b2s[tid] = b2[tid];
    __syncthreads();

    int w = tid >> 5, lane = tid & 31;
    int n = blockIdx.x * 8 + w;
    if (n >= N_NODES) return;

    for (int j = lane; j < EMB; j += 32) {
        float hv = g_H[(size_t)n * EMB + j];
        gsh[w][j] = fmaxf(scs[j] * hv + bss[j], 0.f);
    }
    __syncwarp();
    for (int j = lane; j < EMB; j += 32) {
        float acc = b1s[j];
#pragma unroll 4
        for (int f = 0; f < EMB; f++) acc = fmaf(gsh[w][f], w1s[f * EMB + j], acc);
        zsh[w][j] = fmaxf(acc, 0.f);
    }
    __syncwarp();
    if (lane < 2) {
        float acc = b2s[lane];
#pragma unroll 4
        for (int f = 0; f < EMB; f++) acc = fmaf(zsh[w][f], w2s[f * 2 + lane], acc);
        out[(size_t)n * 2 + lane] = acc;
    }
}

// ------------------------- launch -------------------------
extern "C" void kernel_launch(void* const* d_in, const int* in_sizes, int n_in,
                              void* d_out, int out_size) {
    const float* x     = (const float*)d_in[0];
    const int*   ei    = (const int*)d_in[1];
    const float* Wpre  = (const float*)d_in[2];
    const float* bpre  = (const float*)d_in[3];
    const float* Wpost = (const float*)d_in[4];
    const float* bpost = (const float*)d_in[5];
    const float* Wlin  = (const float*)d_in[6];
    const float* blin  = (const float*)d_in[7];
    const float* gnw   = (const float*)d_in[8];
    const float* gnb   = (const float*)d_in[9];
    const float* gms   = (const float*)d_in[10];
    const float* W1    = (const float*)d_in[11];
    const float* b1    = (const float*)d_in[12];
    const float* W2    = (const float*)d_in[13];
    const float* b2    = (const float*)d_in[14];
    const float* avg   = (const float*)d_in[15];
    const int* src = ei;
    const int* dst = ei + N_EDGES;
    float* out = (float*)d_out;

    const size_t fused_smem = (size_t)SM_TOTAL * sizeof(float);
    cudaFuncSetAttribute(k_fused, cudaFuncAttributeMaxDynamicSharedMemorySize, (int)fused_smem);

    k_zero<<<(N_NODES + 255) / 256, 256>>>();
    k_count<<<(N_EDGES + 255) / 256, 256>>>(dst);
    k_scan<<<1, 1024>>>();
    k_fill<<<(N_EDGES + 255) / 256, 256>>>(src, dst);
    k_sort<<<(N_NODES + 7) / 8, 256>>>();
    dim3 abg(7, 313);
    k_ab<<<abg, 256>>>(x, Wpre, bpre);
    k_fused<<<POST_BLOCKS, FUSED_T, fused_smem>>>(x, Wpost, bpost, Wlin, blin, avg);
    k_norm<<<EMB, 256>>>(gnw, gnb, gms);
    k_head<<<(N_NODES + 7) / 8, 256>>>(W1, b1, W2, b2, out);
}

// round 15
// speedup vs baseline: 1.0666x; 1.0414x over previous
#include <cuda_runtime.h>
#include <math.h>
#include <float.h>

#define N_NODES 20000
#define N_EDGES 320000
#define FDIM 40
#define TG 200          // T*F message dims
#define EMB 40
#define EPS_STD 1e-5f
#define EPS_GN 1e-5f
#define POST_NT 32
#define POST_BLOCKS (N_NODES / POST_NT)   // 625
#define SORT_CAP 128
#define FUSED_T 640
#define FUSED_W 20

// packed f32x2 helpers (bit-identical to two scalar fmaf's)
#define FFMA2(acc, a, b) \
    asm("fma.rn.f32x2 %0, %1, %2, %3;" : "=l"(acc) : "l"(a), "l"(b), "l"(acc))
#define PACK2(out, lo, hi) \
    asm("mov.b64 %0, {%1, %2};" : "=l"(out) : "r"(lo), "r"(hi))
#define UNPACK2(lo, hi, in) \
    asm("mov.b64 {%0, %1}, %2;" : "=r"(lo), "=r"(hi) : "l"(in))

// ------------------------- scratch (device globals) -------------------------
__device__ int   g_deg[N_NODES];
__device__ int   g_off[N_NODES + 1];
__device__ int   g_cur[N_NODES];
__device__ int   g_csr[N_EDGES];
__device__ float g_A[N_NODES * TG];        // x@Wpre_top + b_pre
__device__ float g_B[N_NODES * TG];        // x@Wpre_bot
__device__ float g_H[N_NODES * EMB];       // pre-norm hidden
__device__ float g_psum[POST_BLOCKS * EMB];
__device__ float g_psq[POST_BLOCKS * EMB];
__device__ float g_scale[EMB];
__device__ float g_bias2[EMB];

// ------------------------- CSR build -------------------------
__global__ void k_zero() {
    int i = blockIdx.x * blockDim.x + threadIdx.x;
    if (i < N_NODES) g_deg[i] = 0;
}

__global__ void k_count(const int* __restrict__ dst) {
    int e = blockIdx.x * blockDim.x + threadIdx.x;
    if (e < N_EDGES) atomicAdd(&g_deg[dst[e]], 1);
}

__global__ void k_scan() {
    __shared__ int sp[1024];
    int t = threadIdx.x;
    const int C = 20;  // 1024*20 = 20480 >= N
    int lo = t * C;
    int hi = lo + C; if (hi > N_NODES) hi = N_NODES;
    if (lo > N_NODES) lo = N_NODES;
    int s = 0;
    for (int i = lo; i < hi; i++) s += g_deg[i];
    sp[t] = s;
    __syncthreads();
    for (int o = 1; o < 1024; o <<= 1) {
        int v = (t >= o) ? sp[t - o] : 0;
        __syncthreads();
        sp[t] += v;
        __syncthreads();
    }
    int run = sp[t] - s;  // exclusive
    for (int i = lo; i < hi; i++) {
        g_off[i] = run; g_cur[i] = run;
        run += g_deg[i];
    }
    if (t == 1023) g_off[N_NODES] = sp[1023];
}

__global__ void k_fill(const int* __restrict__ src, const int* __restrict__ dst) {
    int e = blockIdx.x * blockDim.x + threadIdx.x;
    if (e < N_EDGES) {
        int p = atomicAdd(&g_cur[dst[e]], 1);
        g_csr[p] = src[e];
    }
}

// deterministic order: sort each node's neighbor list
__global__ void k_sort() {
    __shared__ int buf[8][SORT_CAP];
    int w = threadIdx.x >> 5, lane = threadIdx.x & 31;
    int n = blockIdx.x * 8 + w;
    if (n >= N_NODES) return;
    int beg = g_off[n];
    int deg = g_off[n + 1] - beg;
    if (deg <= 1 || deg > SORT_CAP) return;
    for (int i = lane; i < deg; i += 32) buf[w][i] = g_csr[beg + i];
    __syncwarp();
    for (int r = 0; r < deg; r++) {
        int start = r & 1;
        for (int i = start + 2 * lane; i + 1 < deg; i += 64) {
            int a = buf[w][i], b = buf[w][i + 1];
            if (a > b) { buf[w][i] = b; buf[w][i + 1] = a; }
        }
        __syncwarp();
    }
    for (int i = lane; i < deg; i += 32) g_csr[beg + i] = buf[w][i];
}

// ------------------------- A/B precompute: [N,40] @ [40,400] -------------------------
__global__ void k_ab(const float* __restrict__ x, const float* __restrict__ Wpre,
                     const float* __restrict__ bpre) {
    __shared__ __align__(16) float xsT[FDIM * 64];  // [k][node]
    __shared__ __align__(16) float wsT[FDIM * 64];  // [k][col]
    int tid = threadIdx.x;
    int c0 = blockIdx.x * 64;  // 0..6 -> cols
    int n0 = blockIdx.y * 64;  // 0..312 -> nodes
    for (int idx = tid; idx < 64 * FDIM; idx += 256) {
        int nl = idx / FDIM, k = idx % FDIM;
        int n = n0 + nl;
        xsT[k * 64 + nl] = (n < N_NODES) ? x[n * FDIM + k] : 0.f;
    }
    for (int idx = tid; idx < 64 * FDIM; idx += 256) {
        int cl = idx / FDIM, k = idx % FDIM;
        int c = c0 + cl;
        float w = 0.f;
        if (c < 2 * TG) {
            if (c < TG) {
                int t = c / FDIM, g = c % FDIM;
                w = Wpre[t * 3200 + k * FDIM + g];
            } else {
                int cc = c - TG;
                int t = cc / FDIM, g = cc % FDIM;
                w = Wpre[t * 3200 + (FDIM + k) * FDIM + g];
            }
        }
        wsT[k * 64 + cl] = w;
    }
    __syncthreads();
    int tx = tid & 15, ty = tid >> 4;
    float acc[4][4];
#pragma unroll
    for (int i = 0; i < 4; i++)
#pragma unroll
        for (int j = 0; j < 4; j++) acc[i][j] = 0.f;
#pragma unroll 4
    for (int k = 0; k < FDIM; k++) {
        float4 xv = *reinterpret_cast<const float4*>(&xsT[k * 64 + ty * 4]);
        float4 wv = *reinterpret_cast<const float4*>(&wsT[k * 64 + tx * 4]);
        float xs[4] = {xv.x, xv.y, xv.z, xv.w};
        float ws[4] = {wv.x, wv.y, wv.z, wv.w};
#pragma unroll
        for (int i = 0; i < 4; i++)
#pragma unroll
            for (int j = 0; j < 4; j++) acc[i][j] = fmaf(xs[i], ws[j], acc[i][j]);
    }
#pragma unroll
    for (int i = 0; i < 4; i++) {
        int n = n0 + ty * 4 + i;
        if (n >= N_NODES) continue;
#pragma unroll
        for (int j = 0; j < 4; j++) {
            int c = c0 + tx * 4 + j;
            if (c >= 2 * TG) continue;
            float v = acc[i][j];
            if (c < TG) g_A[n * TG + c] = v + __ldg(&bpre[c]);
            else        g_B[n * TG + (c - TG)] = v;
        }
    }
}

// ------------------------- fused: aggregation -> post MLP -> W_lin -> norm partials -----
// smem float layout
#define SM_W    0
#define SM_IN   20800              // stride 801 per node
#define SM_X    (SM_IN + 32*801)   // 46432, stride 41
#define SM_S    (SM_X + 32*41)     // 47744
#define SM_Y    (SM_S + 64)        // 47808, stride 41
#define SM_WLIN (SM_Y + 32*41)     // 49120
#define SM_H    (SM_WLIN + 1600)   // 50720, stride 41
#define SM_TOTAL (SM_H + 32*41)    // 52032 floats = 208128 B

__global__ void __launch_bounds__(FUSED_T, 1)
k_fused(const float* __restrict__ x, const float* __restrict__ Wpost,
        const float* __restrict__ bpost, const float* __restrict__ Wlin,
        const float* __restrict__ blin, const float* __restrict__ avgp) {
    extern __shared__ __align__(16) float sm[];
    float* w_sh  = sm + SM_W;
    float* in_sh = sm + SM_IN;
    float* x_sh  = sm + SM_X;
    float* s_sh  = sm + SM_S;
    float* y_sh  = sm + SM_Y;
    float* wlin  = sm + SM_WLIN;
    float* h_sh  = sm + SM_H;
    const int tid = threadIdx.x;          // 640
    const int n0 = blockIdx.x * POST_NT;

    // weight / x preloads (overlap with aggregation latency)
    for (int i = tid; i < 20800; i += FUSED_T) w_sh[i] = Wpost[i];
    for (int i = tid; i < 1600; i += FUSED_T) wlin[i] = Wlin[i];
    for (int i = tid; i < POST_NT * FDIM; i += FUSED_T) {
        int nl = i / FDIM, k = i % FDIM;
        x_sh[nl * 41 + k] = x[(n0 + nl) * FDIM + k];
    }

    const int w = tid >> 5, lane = tid & 31;
    const float avg = *avgp;
    const bool act1 = (lane < 18);        // lane+32 < 50 float4 slots

    // ---- Phase A: aggregation, 20 warps round-robin over 32 nodes ----
    for (int nl = w; nl < POST_NT; nl += FUSED_W) {
        int n = n0 + nl;
        int beg = g_off[n], end = g_off[n + 1];
        int deg = end - beg;
        const float4* Ap = reinterpret_cast<const float4*>(g_A + (size_t)n * TG);
        float4 a0 = __ldg(&Ap[lane]);
        float4 a1 = make_float4(0.f, 0.f, 0.f, 0.f);
        if (act1) a1 = __ldg(&Ap[lane + 32]);

        float S[8], Q[8], S2[8], Q2[8], MN[8], MX[8];
#pragma unroll
        for (int u = 0; u < 8; u++) {
            S[u] = 0.f; Q[u] = 0.f; S2[u] = 0.f; Q2[u] = 0.f;
            MN[u] = FLT_MAX; MX[u] = -FLT_MAX;
        }

        // warp-cooperative index fetch: one coalesced LDG per 32-edge chunk,
        // indices broadcast via shfl -> B-row gathers are the only loads in the loop
        for (int base = beg; base < end; base += 32) {
            int rem = end - base;
            int cnt = rem < 32 ? rem : 32;
            int myidx = 0;
            if (lane < cnt) myidx = __ldg(&g_csr[base + lane]);
            int jj = 0;
            for (; jj + 1 < cnt; jj += 2) {
                int s0 = __shfl_sync(0xffffffffu, myidx, jj);
                int s1 = __shfl_sync(0xffffffffu, myidx, jj + 1);
                const float4* Bp0 = reinterpret_cast<const float4*>(g_B + (size_t)s0 * TG);
                const float4* Bp1 = reinterpret_cast<const float4*>(g_B + (size_t)s1 * TG);
                float4 b0 = __ldg(&Bp0[lane]);
                float4 c0 = __ldg(&Bp1[lane]);
                {
                    float v0 = a0.x + b0.x, v1 = a0.y + b0.y, v2 = a0.z + b0.z, v3 = a0.w + b0.w;
                    S[0] += v0; Q[0] = fmaf(v0, v0, Q[0]); MN[0] = fminf(MN[0], v0); MX[0] = fmaxf(MX[0], v0);
                    S[1] += v1; Q[1] = fmaf(v1, v1, Q[1]); MN[1] = fminf(MN[1], v1); MX[1] = fmaxf(MX[1], v1);
                    S[2] += v2; Q[2] = fmaf(v2, v2, Q[2]); MN[2] = fminf(MN[2], v2); MX[2] = fmaxf(MX[2], v2);
                    S[3] += v3; Q[3] = fmaf(v3, v3, Q[3]); MN[3] = fminf(MN[3], v3); MX[3] = fmaxf(MX[3], v3);
                    float u0 = a0.x + c0.x, u1 = a0.y + c0.y, u2 = a0.z + c0.z, u3 = a0.w + c0.w;
                    S2[0] += u0; Q2[0] = fmaf(u0, u0, Q2[0]); MN[0] = fminf(MN[0], u0); MX[0] = fmaxf(MX[0], u0);
                    S2[1] += u1; Q2[1] = fmaf(u1, u1, Q2[1]); MN[1] = fminf(MN[1], u1); MX[1] = fmaxf(MX[1], u1);
                    S2[2] += u2; Q2[2] = fmaf(u2, u2, Q2[2]); MN[2] = fminf(MN[2], u2); MX[2] = fmaxf(MX[2], u2);
                    S2[3] += u3; Q2[3] = fmaf(u3, u3, Q2[3]); MN[3] = fminf(MN[3], u3); MX[3] = fmaxf(MX[3], u3);
                }
                if (act1) {
                    float4 b1 = __ldg(&Bp0[lane + 32]);
                    float4 c1 = __ldg(&Bp1[lane + 32]);
                    float v0 = a1.x + b1.x, v1 = a1.y + b1.y, v2 = a1.z + b1.z, v3 = a1.w + b1.w;
                    S[4] += v0; Q[4] = fmaf(v0, v0, Q[4]); MN[4] = fminf(MN[4], v0); MX[4] = fmaxf(MX[4], v0);
                    S[5] += v1; Q[5] = fmaf(v1, v1, Q[5]); MN[5] = fminf(MN[5], v1); MX[5] = fmaxf(MX[5], v1);
                    S[6] += v2; Q[6] = fmaf(v2, v2, Q[6]); MN[6] = fminf(MN[6], v2); MX[6] = fmaxf(MX[6], v2);
                    S[7] += v3; Q[7] = fmaf(v3, v3, Q[7]); MN[7] = fminf(MN[7], v3); MX[7] = fmaxf(MX[7], v3);
                    float u0 = a1.x + c1.x, u1 = a1.y + c1.y, u2 = a1.z + c1.z, u3 = a1.w + c1.w;
                    S2[4] += u0; Q2[4] = fmaf(u0, u0, Q2[4]); MN[4] = fminf(MN[4], u0); MX[4] = fmaxf(MX[4], u0);
                    S2[5] += u1; Q2[5] = fmaf(u1, u1, Q2[5]); MN[5] = fminf(MN[5], u1); MX[5] = fmaxf(MX[5], u1);
                    S2[6] += u2; Q2[6] = fmaf(u2, u2, Q2[6]); MN[6] = fminf(MN[6], u2); MX[6] = fmaxf(MX[6], u2);
                    S2[7] += u3; Q2[7] = fmaf(u3, u3, Q2[7]); MN[7] = fminf(MN[7], u3); MX[7] = fmaxf(MX[7], u3);
                }
            }
            if (jj < cnt) {
                int s0 = __shfl_sync(0xffffffffu, myidx, jj);
                const float4* Bp0 = reinterpret_cast<const float4*>(g_B + (size_t)s0 * TG);
                float4 b0 = __ldg(&Bp0[lane]);
                float v0 = a0.x + b0.x, v1 = a0.y + b0.y, v2 = a0.z + b0.z, v3 = a0.w + b0.w;
                S[0] += v0; Q[0] = fmaf(v0, v0, Q[0]); MN[0] = fminf(MN[0], v0); MX[0] = fmaxf(MX[0], v0);
                S[1] += v1; Q[1] = fmaf(v1, v1, Q[1]); MN[1] = fminf(MN[1], v1); MX[1] = fmaxf(MX[1], v1);
                S[2] += v2; Q[2] = fmaf(v2, v2, Q[2]); MN[2] = fminf(MN[2], v2); MX[2] = fmaxf(MX[2], v2);
                S[3] += v3; Q[3] = fmaf(v3, v3, Q[3]); MN[3] = fminf(MN[3], v3); MX[3] = fmaxf(MX[3], v3);
                if (act1) {
                    float4 b1 = __ldg(&Bp0[lane + 32]);
                    float u0 = a1.x + b1.x, u1 = a1.y + b1.y, u2 = a1.z + b1.z, u3 = a1.w + b1.w;
                    S[4] += u0; Q[4] = fmaf(u0, u0, Q[4]); MN[4] = fminf(MN[4], u0); MX[4] = fmaxf(MX[4], u0);
                    S[5] += u1; Q[5] = fmaf(u1, u1, Q[5]); MN[5] = fminf(MN[5], u1); MX[5] = fmaxf(MX[5], u1);
                    S[6] += u2; Q[6] = fmaf(u2, u2, Q[6]); MN[6] = fminf(MN[6], u2); MX[6] = fmaxf(MX[6], u2);
                    S[7] += u3; Q[7] = fmaf(u3, u3, Q[7]); MN[7] = fminf(MN[7], u3); MX[7] = fmaxf(MX[7], u3);
                }
            }
        }
#pragma unroll
        for (int u = 0; u < 8; u++) { S[u] += S2[u]; Q[u] += Q2[u]; }

        float denom = (float)(deg > 1 ? deg : 1);
        float inv = 1.f / denom;
        float* row = in_sh + nl * 801;
#pragma unroll
        for (int u = 0; u < 8; u++) {
            int d = (u < 4) ? (4 * lane + u) : (4 * lane + 124 + u);  // 4*(lane+32)+(u-4)
            if (d < TG) {
                float mean = S[u] * inv;
                float var = Q[u] * inv - mean * mean;
                float stdv = sqrtf(fmaxf(var, 0.f) + EPS_STD);
                float mnv = (deg > 0) ? MN[u] : 0.f;
                float mxv = (deg > 0) ? MX[u] : 0.f;
                int t = d / FDIM, f = d - t * FDIM;
                float* o = row + t * 160 + f;
                o[0] = mean; o[40] = mnv; o[80] = mxv; o[120] = stdv;
            }
        }
        if (lane == 0) {
            float logd = logf(denom + 1.f);
            s_sh[nl * 2] = logd / avg;
            s_sh[nl * 2 + 1] = avg / logd;
        }
    }
    __syncthreads();

    // ---- Phase B: per-(tower, out-pair, node) GEMM, f32x2-packed, smem weights ----
    {
        const int t = w >> 2;       // 0..4
        const int gp = w & 3;       // 0..3 -> outputs 2*gp, 2*gp+1
        const int nl = lane;
        const float* wt = w_sh + t * 4160 + gp * 2;   // 8-byte aligned
        unsigned long long accx = 0ull, acc1 = 0ull, acc2 = 0ull, acc3 = 0ull;
        const float* xr = x_sh + nl * 41;
#pragma unroll 4
        for (int k = 0; k < FDIM; k++) {
            float v = xr[k];
            unsigned long long vv;
            PACK2(vv, __float_as_uint(v), __float_as_uint(v));
            unsigned long long wv = *reinterpret_cast<const unsigned long long*>(wt + k * 8);
            FFMA2(accx, vv, wv);
        }
        const float* ar = in_sh + nl * 801 + t * 160;
#pragma unroll 4
        for (int k = 0; k < 160; k++) {
            float v = ar[k];
            unsigned long long vv;
            PACK2(vv, __float_as_uint(v), __float_as_uint(v));
            unsigned long long w1 = *reinterpret_cast<const unsigned long long*>(wt + (40 + k) * 8);
            unsigned long long w2 = *reinterpret_cast<const unsigned long long*>(wt + (200 + k) * 8);
            unsigned long long w3 = *reinterpret_cast<const unsigned long long*>(wt + (360 + k) * 8);
            FFMA2(acc1, vv, w1);
            FFMA2(acc2, vv, w2);
            FFMA2(acc3, vv, w3);
        }
        unsigned int x0i, x1i, a10i, a11i, a20i, a21i, a30i, a31i;
        UNPACK2(x0i, x1i, accx);
        UNPACK2(a10i, a11i, acc1);
        UNPACK2(a20i, a21i, acc2);
        UNPACK2(a30i, a31i, acc3);
        float ax0 = __uint_as_float(x0i),  ax1 = __uint_as_float(x1i);
        float a10 = __uint_as_float(a10i), a11 = __uint_as_float(a11i);
        float a20 = __uint_as_float(a20i), a21 = __uint_as_float(a21i);
        float a30 = __uint_as_float(a30i), a31 = __uint_as_float(a31i);
        float s1 = s_sh[nl * 2], s2 = s_sh[nl * 2 + 1];
        float y0 = ax0 + a10 + s1 * a20 + s2 * a30 + __ldg(&bpost[t * 8 + gp * 2]);
        float y1 = ax1 + a11 + s1 * a21 + s2 * a31 + __ldg(&bpost[t * 8 + gp * 2 + 1]);
        y_sh[nl * 41 + t * 8 + gp * 2]     = y0;
        y_sh[nl * 41 + t * 8 + gp * 2 + 1] = y1;
    }
    __syncthreads();

    // ---- W_lin: 32 nodes x 40 outs = 1280 tasks ----
    for (int r = 0; r < 2; r++) {
        int task = tid + r * FUSED_T;
        int nl = task / EMB, j = task % EMB;
        float acc = __ldg(&blin[j]);
        const float* yr = y_sh + nl * 41;
#pragma unroll 4
        for (int o = 0; o < EMB; o++) acc = fmaf(yr[o], wlin[o * EMB + j], acc);
        h_sh[nl * 41 + j] = acc;
        g_H[(size_t)(n0 + nl) * EMB + j] = acc;
    }
    __syncthreads();

    // ---- GraphNorm partials ----
    if (tid < EMB) {
        float s = 0.f, q = 0.f;
        for (int nl = 0; nl < POST_NT; nl++) {
            float v = h_sh[nl * 41 + tid];
            s += v;
            q = fmaf(v, v, q);
        }
        g_psum[blockIdx.x * EMB + tid] = s;
        g_psq[blockIdx.x * EMB + tid] = q;
    }
}

// ------------------------- GraphNorm finalize (parallel, fixed tree) -------------------------
__global__ void k_norm(const float* __restrict__ gnw, const float* __restrict__ gnb,
                       const float* __restrict__ gms) {
    __shared__ float sbuf[256], qbuf[256];
    int j = blockIdx.x;          // 40 blocks, one per channel
    int t = threadIdx.x;         // 256
    float s = 0.f, q = 0.f;
    for (int b = t; b < POST_BLOCKS; b += 256) {
        s += g_psum[b * EMB + j];
        q += g_psq[b * EMB + j];
    }
    sbuf[t] = s; qbuf[t] = q;
    __syncthreads();
    for (int o = 128; o > 0; o >>= 1) {
        if (t < o) { sbuf[t] += sbuf[t + o]; qbuf[t] += qbuf[t + o]; }
        __syncthreads();
    }
    if (t == 0) {
        float mu  = sbuf[0] / (float)N_NODES;
        float msq = qbuf[0] / (float)N_NODES;
        float ms  = gms[j];
        float var = msq - 2.f * ms * mu * mu + ms * ms * mu * mu;
        float scale = gnw[j] * rsqrtf(var + EPS_GN);
        g_scale[j] = scale;
        g_bias2[j] = gnb[j] - scale * ms * mu;
    }
}

// ------------------------- head: relu(norm) -> relu(@W1+b1) -> @W2+b2 -------------------------
__global__ void k_head(const float* __restrict__ W1, const float* __restrict__ b1,
                       const float* __restrict__ W2, const float* __restrict__ b2,
                       float* __restrict__ out) {
    __shared__ float w1s[1600], w2s[80], b1s[40], b2s[2], scs[40], bss[40];
    __shared__ float gsh[8][40], zsh[8][40];
    int tid = threadIdx.x;
    for (int idx = tid; idx < 1600; idx += 256) w1s[idx] = W1[idx];
    if (tid < 80) w2s[tid] = W2[tid];
    if (tid < 40) { b1s[tid] = b1[tid]; scs[tid] = g_scale[tid]; bss[tid] = g_bias2[tid]; }
    if (tid < 2)  b2s[tid] = b2[tid];
    __syncthreads();

    int w = tid >> 5, lane = tid & 31;
    int n = blockIdx.x * 8 + w;
    if (n >= N_NODES) return;

    for (int j = lane; j < EMB; j += 32) {
        float hv = g_H[(size_t)n * EMB + j];
        gsh[w][j] = fmaxf(scs[j] * hv + bss[j], 0.f);
    }
    __syncwarp();
    for (int j = lane; j < EMB; j += 32) {
        float acc = b1s[j];
#pragma unroll 4
        for (int f = 0; f < EMB; f++) acc = fmaf(gsh[w][f], w1s[f * EMB + j], acc);
        zsh[w][j] = fmaxf(acc, 0.f);
    }
    __syncwarp();
    if (lane < 2) {
        float acc = b2s[lane];
#pragma unroll 4
        for (int f = 0; f < EMB; f++) acc = fmaf(zsh[w][f], w2s[f * 2 + lane], acc);
        out[(size_t)n * 2 + lane] = acc;
    }
}

// ------------------------- launch -------------------------
extern "C" void kernel_launch(void* const* d_in, const int* in_sizes, int n_in,
                              void* d_out, int out_size) {
    const float* x     = (const float*)d_in[0];
    const int*   ei    = (const int*)d_in[1];
    const float* Wpre  = (const float*)d_in[2];
    const float* bpre  = (const float*)d_in[3];
    const float* Wpost = (const float*)d_in[4];
    const float* bpost = (const float*)d_in[5];
    const float* Wlin  = (const float*)d_in[6];
    const float* blin  = (const float*)d_in[7];
    const float* gnw   = (const float*)d_in[8];
    const float* gnb   = (const float*)d_in[9];
    const float* gms   = (const float*)d_in[10];
    const float* W1    = (const float*)d_in[11];
    const float* b1    = (const float*)d_in[12];
    const float* W2    = (const float*)d_in[13];
    const float* b2    = (const float*)d_in[14];
    const float* avg   = (const float*)d_in[15];
    const int* src = ei;
    const int* dst = ei + N_EDGES;
    float* out = (float*)d_out;

    // side stream + events for overlapping k_ab with the CSR chain.
    // Created once on the first (uncaptured) call; reused thereafter.
    static cudaStream_t s_ab = nullptr;
    static cudaEvent_t ev_fork = nullptr, ev_join = nullptr;
    if (s_ab == nullptr) {
        cudaStreamCreateWithFlags(&s_ab, cudaStreamNonBlocking);
        cudaEventCreateWithFlags(&ev_fork, cudaEventDisableTiming);
        cudaEventCreateWithFlags(&ev_join, cudaEventDisableTiming);
    }

    const size_t fused_smem = (size_t)SM_TOTAL * sizeof(float);
    cudaFuncSetAttribute(k_fused, cudaFuncAttributeMaxDynamicSharedMemorySize, (int)fused_smem);

    // fork: k_ab runs concurrently with the CSR build chain
    cudaEventRecord(ev_fork, 0);
    cudaStreamWaitEvent(s_ab, ev_fork, 0);
    dim3 abg(7, 313);
    k_ab<<<abg, 256, 0, s_ab>>>(x, Wpre, bpre);
    cudaEventRecord(ev_join, s_ab);

    k_zero<<<(N_NODES + 255) / 256, 256>>>();
    k_count<<<(N_EDGES + 255) / 256, 256>>>(dst);
    k_scan<<<1, 1024>>>();
    k_fill<<<(N_EDGES + 255) / 256, 256>>>(src, dst);
    k_sort<<<(N_NODES + 7) / 8, 256>>>();

    // join: k_fused needs both the CSR chain (default stream order) and k_ab
    cudaStreamWaitEvent(0, ev_join, 0);
    k_fused<<<POST_BLOCKS, FUSED_T, fused_smem>>>(x, Wpost, bpost, Wlin, blin, avg);
    k_norm<<<EMB, 256>>>(gnw, gnb, gms);
    k_head<<<(N_NODES + 7) / 8, 256>>>(W1, b1, W2, b2, out);
}

// round 17
// speedup vs baseline: 1.1649x; 1.0921x over previous
#include <cuda_runtime.h>
#include <math.h>
#include <float.h>

#define N_NODES 20000
#define N_EDGES 320000
#define FDIM 40
#define TG 200          // T*F message dims
#define EMB 40
#define EPS_STD 1e-5f
#define EPS_GN 1e-5f
#define POST_NT 32
#define POST_BLOCKS (N_NODES / POST_NT)   // 625
#define SORT_CAP 128
#define FUSED_T 640
#define FUSED_W 20

// packed f32x2 helpers (bit-identical to two scalar fmaf's)
#define FFMA2(acc, a, b) \
    asm("fma.rn.f32x2 %0, %1, %2, %3;" : "=l"(acc) : "l"(a), "l"(b), "l"(acc))
#define PACK2(out, lo, hi) \
    asm("mov.b64 %0, {%1, %2};" : "=l"(out) : "r"(lo), "r"(hi))
#define UNPACK2(lo, hi, in) \
    asm("mov.b64 {%0, %1}, %2;" : "=r"(lo), "=r"(hi) : "l"(in))

// ------------------------- scratch (device globals) -------------------------
__device__ int   g_deg[N_NODES];
__device__ int   g_off[N_NODES];
__device__ int   g_cur[N_NODES];
__device__ int   g_total;
__device__ int   g_csr[N_EDGES];
__device__ float g_A[N_NODES * TG];        // x@Wpre_top + b_pre
__device__ float g_B[N_NODES * TG];        // x@Wpre_bot
__device__ float g_H[N_NODES * EMB];       // pre-norm hidden
__device__ float g_psum[POST_BLOCKS * EMB];
__device__ float g_psq[POST_BLOCKS * EMB];
__device__ float g_scale[EMB];
__device__ float g_bias2[EMB];

// ------------------------- CSR build -------------------------
__global__ void k_zero() {
    int i = blockIdx.x * blockDim.x + threadIdx.x;
    if (i < N_NODES) g_deg[i] = 0;
    if (i == 0) g_total = 0;
}

__global__ void k_count(const int* __restrict__ dst) {
    int e = blockIdx.x * blockDim.x + threadIdx.x;
    if (e < N_EDGES) atomicAdd(&g_deg[dst[e]], 1);
}

// full-chip offset assignment: per-block smem scan + one atomicAdd per block.
// Placement across blocks is allocation-order dependent, but per-node segments
// are disjoint and later sorted, so the final output is placement-invariant.
__global__ void k_offsets() {
    __shared__ int sdata[256];
    __shared__ int sbase;
    int t = threadIdx.x;
    int i = blockIdx.x * 256 + t;
    int d = (i < N_NODES) ? g_deg[i] : 0;
    sdata[t] = d;
    __syncthreads();
    for (int o = 1; o < 256; o <<= 1) {
        int v = (t >= o) ? sdata[t - o] : 0;
        __syncthreads();
        sdata[t] += v;
        __syncthreads();
    }
    if (t == 255) sbase = atomicAdd(&g_total, sdata[255]);
    __syncthreads();
    int excl = sdata[t] - d + sbase;
    if (i < N_NODES) {
        g_off[i] = excl;
        g_cur[i] = excl;
    }
}

__global__ void k_fill(const int* __restrict__ src, const int* __restrict__ dst) {
    int e = blockIdx.x * blockDim.x + threadIdx.x;
    if (e < N_EDGES) {
        int p = atomicAdd(&g_cur[dst[e]], 1);
        g_csr[p] = src[e];
    }
}

// deterministic order: sort each node's neighbor list
__global__ void k_sort() {
    __shared__ int buf[8][SORT_CAP];
    int w = threadIdx.x >> 5, lane = threadIdx.x & 31;
    int n = blockIdx.x * 8 + w;
    if (n >= N_NODES) return;
    int beg = g_off[n];
    int deg = g_deg[n];
    if (deg <= 1 || deg > SORT_CAP) return;
    for (int i = lane; i < deg; i += 32) buf[w][i] = g_csr[beg + i];
    __syncwarp();
    for (int r = 0; r < deg; r++) {
        int start = r & 1;
        for (int i = start + 2 * lane; i + 1 < deg; i += 64) {
            int a = buf[w][i], b = buf[w][i + 1];
            if (a > b) { buf[w][i] = b; buf[w][i + 1] = a; }
        }
        __syncwarp();
    }
    for (int i = lane; i < deg; i += 32) g_csr[beg + i] = buf[w][i];
}

// ------------------------- A/B precompute: [N,40] @ [40,400] -------------------------
__global__ void k_ab(const float* __restrict__ x, const float* __restrict__ Wpre,
                     const float* __restrict__ bpre) {
    __shared__ __align__(16) float xsT[FDIM * 64];  // [k][node]
    __shared__ __align__(16) float wsT[FDIM * 64];  // [k][col]
    int tid = threadIdx.x;
    int c0 = blockIdx.x * 64;  // 0..6 -> cols
    int n0 = blockIdx.y * 64;  // 0..312 -> nodes
    for (int idx = tid; idx < 64 * FDIM; idx += 256) {
        int nl = idx / FDIM, k = idx % FDIM;
        int n = n0 + nl;
        xsT[k * 64 + nl] = (n < N_NODES) ? x[n * FDIM + k] : 0.f;
    }
    for (int idx = tid; idx < 64 * FDIM; idx += 256) {
        int cl = idx / FDIM, k = idx % FDIM;
        int c = c0 + cl;
        float w = 0.f;
        if (c < 2 * TG) {
            if (c < TG) {
                int t = c / FDIM, g = c % FDIM;
                w = Wpre[t * 3200 + k * FDIM + g];
            } else {
                int cc = c - TG;
                int t = cc / FDIM, g = cc % FDIM;
                w = Wpre[t * 3200 + (FDIM + k) * FDIM + g];
            }
        }
        wsT[k * 64 + cl] = w;
    }
    __syncthreads();
    int tx = tid & 15, ty = tid >> 4;
    float acc[4][4];
#pragma unroll
    for (int i = 0; i < 4; i++)
#pragma unroll
        for (int j = 0; j < 4; j++) acc[i][j] = 0.f;
#pragma unroll 4
    for (int k = 0; k < FDIM; k++) {
        float4 xv = *reinterpret_cast<const float4*>(&xsT[k * 64 + ty * 4]);
        float4 wv = *reinterpret_cast<const float4*>(&wsT[k * 64 + tx * 4]);
        float xs[4] = {xv.x, xv.y, xv.z, xv.w};
        float ws[4] = {wv.x, wv.y, wv.z, wv.w};
#pragma unroll
        for (int i = 0; i < 4; i++)
#pragma unroll
            for (int j = 0; j < 4; j++) acc[i][j] = fmaf(xs[i], ws[j], acc[i][j]);
    }
#pragma unroll
    for (int i = 0; i < 4; i++) {
        int n = n0 + ty * 4 + i;
        if (n >= N_NODES) continue;
#pragma unroll
        for (int j = 0; j < 4; j++) {
            int c = c0 + tx * 4 + j;
            if (c >= 2 * TG) continue;
            float v = acc[i][j];
            if (c < TG) g_A[n * TG + c] = v + __ldg(&bpre[c]);
            else        g_B[n * TG + (c - TG)] = v;
        }
    }
}

// ------------------------- fused: aggregation -> post MLP -> W_lin -> norm partials -----
// smem float layout
#define SM_W    0
#define SM_IN   20800              // stride 801 per node
#define SM_X    (SM_IN + 32*801)   // 46432, stride 41
#define SM_S    (SM_X + 32*41)     // 47744
#define SM_Y    (SM_S + 64)        // 47808, stride 41
#define SM_WLIN (SM_Y + 32*41)     // 49120
#define SM_H    (SM_WLIN + 1600)   // 50720, stride 41
#define SM_TOTAL (SM_H + 32*41)    // 52032 floats = 208128 B

__global__ void __launch_bounds__(FUSED_T, 1)
k_fused(const float* __restrict__ x, const float* __restrict__ Wpost,
        const float* __restrict__ bpost, const float* __restrict__ Wlin,
        const float* __restrict__ blin, const float* __restrict__ avgp) {
    extern __shared__ __align__(16) float sm[];
    float* w_sh  = sm + SM_W;
    float* in_sh = sm + SM_IN;
    float* x_sh  = sm + SM_X;
    float* s_sh  = sm + SM_S;
    float* y_sh  = sm + SM_Y;
    float* wlin  = sm + SM_WLIN;
    float* h_sh  = sm + SM_H;
    const int tid = threadIdx.x;          // 640
    const int n0 = blockIdx.x * POST_NT;

    // weight / x preloads (overlap with aggregation latency)
    for (int i = tid; i < 20800; i += FUSED_T) w_sh[i] = Wpost[i];
    for (int i = tid; i < 1600; i += FUSED_T) wlin[i] = Wlin[i];
    for (int i = tid; i < POST_NT * FDIM; i += FUSED_T) {
        int nl = i / FDIM, k = i % FDIM;
        x_sh[nl * 41 + k] = x[(n0 + nl) * FDIM + k];
    }

    const int w = tid >> 5, lane = tid & 31;
    const float avg = *avgp;
    const bool act1 = (lane < 18);        // lane+32 < 50 float4 slots

    // ---- Phase A: aggregation, 20 warps round-robin over 32 nodes ----
    for (int nl = w; nl < POST_NT; nl += FUSED_W) {
        int n = n0 + nl;
        int beg = g_off[n];
        int deg = g_deg[n];
        int end = beg + deg;
        const float4* Ap = reinterpret_cast<const float4*>(g_A + (size_t)n * TG);
        float4 a0 = __ldg(&Ap[lane]);
        float4 a1 = make_float4(0.f, 0.f, 0.f, 0.f);
        if (act1) a1 = __ldg(&Ap[lane + 32]);

        float S[8], Q[8], S2[8], Q2[8], MN[8], MX[8];
#pragma unroll
        for (int u = 0; u < 8; u++) {
            S[u] = 0.f; Q[u] = 0.f; S2[u] = 0.f; Q2[u] = 0.f;
            MN[u] = FLT_MAX; MX[u] = -FLT_MAX;
        }

        // warp-cooperative index fetch: one coalesced LDG per 32-edge chunk,
        // indices broadcast via shfl -> B-row gathers are the only loads in the loop
        for (int base = beg; base < end; base += 32) {
            int rem = end - base;
            int cnt = rem < 32 ? rem : 32;
            int myidx = 0;
            if (lane < cnt) myidx = __ldg(&g_csr[base + lane]);
            int jj = 0;
            for (; jj + 1 < cnt; jj += 2) {
                int s0 = __shfl_sync(0xffffffffu, myidx, jj);
                int s1 = __shfl_sync(0xffffffffu, myidx, jj + 1);
                const float4* Bp0 = reinterpret_cast<const float4*>(g_B + (size_t)s0 * TG);
                const float4* Bp1 = reinterpret_cast<const float4*>(g_B + (size_t)s1 * TG);
                float4 b0 = __ldg(&Bp0[lane]);
                float4 c0 = __ldg(&Bp1[lane]);
                {
                    float v0 = a0.x + b0.x, v1 = a0.y + b0.y, v2 = a0.z + b0.z, v3 = a0.w + b0.w;
                    S[0] += v0; Q[0] = fmaf(v0, v0, Q[0]); MN[0] = fminf(MN[0], v0); MX[0] = fmaxf(MX[0], v0);
                    S[1] += v1; Q[1] = fmaf(v1, v1, Q[1]); MN[1] = fminf(MN[1], v1); MX[1] = fmaxf(MX[1], v1);
                    S[2] += v2; Q[2] = fmaf(v2, v2, Q[2]); MN[2] = fminf(MN[2], v2); MX[2] = fmaxf(MX[2], v2);
                    S[3] += v3; Q[3] = fmaf(v3, v3, Q[3]); MN[3] = fminf(MN[3], v3); MX[3] = fmaxf(MX[3], v3);
                    float u0 = a0.x + c0.x, u1 = a0.y + c0.y, u2 = a0.z + c0.z, u3 = a0.w + c0.w;
                    S2[0] += u0; Q2[0] = fmaf(u0, u0, Q2[0]); MN[0] = fminf(MN[0], u0); MX[0] = fmaxf(MX[0], u0);
                    S2[1] += u1; Q2[1] = fmaf(u1, u1, Q2[1]); MN[1] = fminf(MN[1], u1); MX[1] = fmaxf(MX[1], u1);
                    S2[2] += u2; Q2[2] = fmaf(u2, u2, Q2[2]); MN[2] = fminf(MN[2], u2); MX[2] = fmaxf(MX[2], u2);
                    S2[3] += u3; Q2[3] = fmaf(u3, u3, Q2[3]); MN[3] = fminf(MN[3], u3); MX[3] = fmaxf(MX[3], u3);
                }
                if (act1) {
                    float4 b1 = __ldg(&Bp0[lane + 32]);
                    float4 c1 = __ldg(&Bp1[lane + 32]);
                    float v0 = a1.x + b1.x, v1 = a1.y + b1.y, v2 = a1.z + b1.z, v3 = a1.w + b1.w;
                    S[4] += v0; Q[4] = fmaf(v0, v0, Q[4]); MN[4] = fminf(MN[4], v0); MX[4] = fmaxf(MX[4], v0);
                    S[5] += v1; Q[5] = fmaf(v1, v1, Q[5]); MN[5] = fminf(MN[5], v1); MX[5] = fmaxf(MX[5], v1);
                    S[6] += v2; Q[6] = fmaf(v2, v2, Q[6]); MN[6] = fminf(MN[6], v2); MX[6] = fmaxf(MX[6], v2);
                    S[7] += v3; Q[7] = fmaf(v3, v3, Q[7]); MN[7] = fminf(MN[7], v3); MX[7] = fmaxf(MX[7], v3);
                    float u0 = a1.x + c1.x, u1 = a1.y + c1.y, u2 = a1.z + c1.z, u3 = a1.w + c1.w;
                    S2[4] += u0; Q2[4] = fmaf(u0, u0, Q2[4]); MN[4] = fminf(MN[4], u0); MX[4] = fmaxf(MX[4], u0);
                    S2[5] += u1; Q2[5] = fmaf(u1, u1, Q2[5]); MN[5] = fminf(MN[5], u1); MX[5] = fmaxf(MX[5], u1);
                    S2[6] += u2; Q2[6] = fmaf(u2, u2, Q2[6]); MN[6] = fminf(MN[6], u2); MX[6] = fmaxf(MX[6], u2);
                    S2[7] += u3; Q2[7] = fmaf(u3, u3, Q2[7]); MN[7] = fminf(MN[7], u3); MX[7] = fmaxf(MX[7], u3);
                }
            }
            if (jj < cnt) {
                int s0 = __shfl_sync(0xffffffffu, myidx, jj);
                const float4* Bp0 = reinterpret_cast<const float4*>(g_B + (size_t)s0 * TG);
                float4 b0 = __ldg(&Bp0[lane]);
                float v0 = a0.x + b0.x, v1 = a0.y + b0.y, v2 = a0.z + b0.z, v3 = a0.w + b0.w;
                S[0] += v0; Q[0] = fmaf(v0, v0, Q[0]); MN[0] = fminf(MN[0], v0); MX[0] = fmaxf(MX[0], v0);
                S[1] += v1; Q[1] = fmaf(v1, v1, Q[1]); MN[1] = fminf(MN[1], v1); MX[1] = fmaxf(MX[1], v1);
                S[2] += v2; Q[2] = fmaf(v2, v2, Q[2]); MN[2] = fminf(MN[2], v2); MX[2] = fmaxf(MX[2], v2);
                S[3] += v3; Q[3] = fmaf(v3, v3, Q[3]); MN[3] = fminf(MN[3], v3); MX[3] = fmaxf(MX[3], v3);
                if (act1) {
                    float4 b1 = __ldg(&Bp0[lane + 32]);
                    float u0 = a1.x + b1.x, u1 = a1.y + b1.y, u2 = a1.z + b1.z, u3 = a1.w + b1.w;
                    S[4] += u0; Q[4] = fmaf(u0, u0, Q[4]); MN[4] = fminf(MN[4], u0); MX[4] = fmaxf(MX[4], u0);
                    S[5] += u1; Q[5] = fmaf(u1, u1, Q[5]); MN[5] = fminf(MN[5], u1); MX[5] = fmaxf(MX[5], u1);
                    S[6] += u2; Q[6] = fmaf(u2, u2, Q[6]); MN[6] = fminf(MN[6], u2); MX[6] = fmaxf(MX[6], u2);
                    S[7] += u3; Q[7] = fmaf(u3, u3, Q[7]); MN[7] = fminf(MN[7], u3); MX[7] = fmaxf(MX[7], u3);
                }
            }
        }
#pragma unroll
        for (int u = 0; u < 8; u++) { S[u] += S2[u]; Q[u] += Q2[u]; }

        float denom = (float)(deg > 1 ? deg : 1);
        float inv = 1.f / denom;
        float* row = in_sh + nl * 801;
#pragma unroll
        for (int u = 0; u < 8; u++) {
            int d = (u < 4) ? (4 * lane + u) : (4 * lane + 124 + u);  // 4*(lane+32)+(u-4)
            if (d < TG) {
                float mean = S[u] * inv;
                float var = Q[u] * inv - mean * mean;
                float stdv = sqrtf(fmaxf(var, 0.f) + EPS_STD);
                float mnv = (deg > 0) ? MN[u] : 0.f;
                float mxv = (deg > 0) ? MX[u] : 0.f;
                int t = d / FDIM, f = d - t * FDIM;
                float* o = row + t * 160 + f;
                o[0] = mean; o[40] = mnv; o[80] = mxv; o[120] = stdv;
            }
        }
        if (lane == 0) {
            float logd = logf(denom + 1.f);
            s_sh[nl * 2] = logd / avg;
            s_sh[nl * 2 + 1] = avg / logd;
        }
    }
    __syncthreads();

    // ---- Phase B: per-(tower, out-pair, node) GEMM, f32x2-packed, smem weights ----
    {
        const int t = w >> 2;       // 0..4
        const int gp = w & 3;       // 0..3 -> outputs 2*gp, 2*gp+1
        const int nl = lane;
        const float* wt = w_sh + t * 4160 + gp * 2;   // 8-byte aligned
        unsigned long long accx = 0ull, acc1 = 0ull, acc2 = 0ull, acc3 = 0ull;
        const float* xr = x_sh + nl * 41;
#pragma unroll 4
        for (int k = 0; k < FDIM; k++) {
            float v = xr[k];
            unsigned long long vv;
            PACK2(vv, __float_as_uint(v), __float_as_uint(v));
            unsigned long long wv = *reinterpret_cast<const unsigned long long*>(wt + k * 8);
            FFMA2(accx, vv, wv);
        }
        const float* ar = in_sh + nl * 801 + t * 160;
#pragma unroll 4
        for (int k = 0; k < 160; k++) {
            float v = ar[k];
            unsigned long long vv;
            PACK2(vv, __float_as_uint(v), __float_as_uint(v));
            unsigned long long w1 = *reinterpret_cast<const unsigned long long*>(wt + (40 + k) * 8);
            unsigned long long w2 = *reinterpret_cast<const unsigned long long*>(wt + (200 + k) * 8);
            unsigned long long w3 = *reinterpret_cast<const unsigned long long*>(wt + (360 + k) * 8);
            FFMA2(acc1, vv, w1);
            FFMA2(acc2, vv, w2);
            FFMA2(acc3, vv, w3);
        }
        unsigned int x0i, x1i, a10i, a11i, a20i, a21i, a30i, a31i;
        UNPACK2(x0i, x1i, accx);
        UNPACK2(a10i, a11i, acc1);
        UNPACK2(a20i, a21i, acc2);
        UNPACK2(a30i, a31i, acc3);
        float ax0 = __uint_as_float(x0i),  ax1 = __uint_as_float(x1i);
        float a10 = __uint_as_float(a10i), a11 = __uint_as_float(a11i);
        float a20 = __uint_as_float(a20i), a21 = __uint_as_float(a21i);
        float a30 = __uint_as_float(a30i), a31 = __uint_as_float(a31i);
        float s1 = s_sh[nl * 2], s2 = s_sh[nl * 2 + 1];
        float y0 = ax0 + a10 + s1 * a20 + s2 * a30 + __ldg(&bpost[t * 8 + gp * 2]);
        float y1 = ax1 + a11 + s1 * a21 + s2 * a31 + __ldg(&bpost[t * 8 + gp * 2 + 1]);
        y_sh[nl * 41 + t * 8 + gp * 2]     = y0;
        y_sh[nl * 41 + t * 8 + gp * 2 + 1] = y1;
    }
    __syncthreads();

    // ---- W_lin: 32 nodes x 40 outs = 1280 tasks ----
    for (int r = 0; r < 2; r++) {
        int task = tid + r * FUSED_T;
        int nl = task / EMB, j = task % EMB;
        float acc = __ldg(&blin[j]);
        const float* yr = y_sh + nl * 41;
#pragma unroll 4
        for (int o = 0; o < EMB; o++) acc = fmaf(yr[o], wlin[o * EMB + j], acc);
        h_sh[nl * 41 + j] = acc;
        g_H[(size_t)(n0 + nl) * EMB + j] = acc;
    }
    __syncthreads();

    // ---- GraphNorm partials ----
    if (tid < EMB) {
        float s = 0.f, q = 0.f;
        for (int nl = 0; nl < POST_NT; nl++) {
            float v = h_sh[nl * 41 + tid];
            s += v;
            q = fmaf(v, v, q);
        }
        g_psum[blockIdx.x * EMB + tid] = s;
        g_psq[blockIdx.x * EMB + tid] = q;
    }
}

// ------------------------- GraphNorm finalize (parallel, fixed tree) -------------------------
__global__ void k_norm(const float* __restrict__ gnw, const float* __restrict__ gnb,
                       const float* __restrict__ gms) {
    __shared__ float sbuf[256], qbuf[256];
    int j = blockIdx.x;          // 40 blocks, one per channel
    int t = threadIdx.x;         // 256
    float s = 0.f, q = 0.f;
    for (int b = t; b < POST_BLOCKS; b += 256) {
        s += g_psum[b * EMB + j];
        q += g_psq[b * EMB + j];
    }
    sbuf[t] = s; qbuf[t] = q;
    __syncthreads();
    for (int o = 128; o > 0; o >>= 1) {
        if (t < o) { sbuf[t] += sbuf[t + o]; qbuf[t] += qbuf[t + o]; }
        __syncthreads();
    }
    if (t == 0) {
        float mu  = sbuf[0] / (float)N_NODES;
        float msq = qbuf[0] / (float)N_NODES;
        float ms  = gms[j];
        float var = msq - 2.f * ms * mu * mu + ms * ms * mu * mu;
        float scale = gnw[j] * rsqrtf(var + EPS_GN);
        g_scale[j] = scale;
        g_bias2[j] = gnb[j] - scale * ms * mu;
    }
}

// ------------------------- head: relu(norm) -> relu(@W1+b1) -> @W2+b2 -------------------------
__global__ void k_head(const float* __restrict__ W1, const float* __restrict__ b1,
                       const float* __restrict__ W2, const float* __restrict__ b2,
                       float* __restrict__ out) {
    __shared__ float w1s[1600], w2s[80], b1s[40], b2s[2], scs[40], bss[40];
    __shared__ float gsh[8][40], zsh[8][40];
    int tid = threadIdx.x;
    for (int idx = tid; idx < 1600; idx += 256) w1s[idx] = W1[idx];
    if (tid < 80) w2s[tid] = W2[tid];
    if (tid < 40) { b1s[tid] = b1[tid]; scs[tid] = g_scale[tid]; bss[tid] = g_bias2[tid]; }
    if (tid < 2)  b2s[tid] = b2[tid];
    __syncthreads();

    int w = tid >> 5, lane = tid & 31;
    int n = blockIdx.x * 8 + w;
    if (n >= N_NODES) return;

    for (int j = lane; j < EMB; j += 32) {
        float hv = g_H[(size_t)n * EMB + j];
        gsh[w][j] = fmaxf(scs[j] * hv + bss[j], 0.f);
    }
    __syncwarp();
    for (int j = lane; j < EMB; j += 32) {
        float acc = b1s[j];
#pragma unroll 4
        for (int f = 0; f < EMB; f++) acc = fmaf(gsh[w][f], w1s[f * EMB + j], acc);
        zsh[w][j] = fmaxf(acc, 0.f);
    }
    __syncwarp();
    if (lane < 2) {
        float acc = b2s[lane];
#pragma unroll 4
        for (int f = 0; f < EMB; f++) acc = fmaf(zsh[w][f], w2s[f * 2 + lane], acc);
        out[(size_t)n * 2 + lane] = acc;
    }
}

// ------------------------- launch -------------------------
extern "C" void kernel_launch(void* const* d_in, const int* in_sizes, int n_in,
                              void* d_out, int out_size) {
    const float* x     = (const float*)d_in[0];
    const int*   ei    = (const int*)d_in[1];
    const float* Wpre  = (const float*)d_in[2];
    const float* bpre  = (const float*)d_in[3];
    const float* Wpost = (const float*)d_in[4];
    const float* bpost = (const float*)d_in[5];
    const float* Wlin  = (const float*)d_in[6];
    const float* blin  = (const float*)d_in[7];
    const float* gnw   = (const float*)d_in[8];
    const float* gnb   = (const float*)d_in[9];
    const float* gms   = (const float*)d_in[10];
    const float* W1    = (const float*)d_in[11];
    const float* b1    = (const float*)d_in[12];
    const float* W2    = (const float*)d_in[13];
    const float* b2    = (const float*)d_in[14];
    const float* avg   = (const float*)d_in[15];
    const int* src = ei;
    const int* dst = ei + N_EDGES;
    float* out = (float*)d_out;

    // side stream + events for overlapping k_ab with the CSR chain.
    static cudaStream_t s_ab = nullptr;
    static cudaEvent_t ev_fork = nullptr, ev_join = nullptr;
    if (s_ab == nullptr) {
        cudaStreamCreateWithFlags(&s_ab, cudaStreamNonBlocking);
        cudaEventCreateWithFlags(&ev_fork, cudaEventDisableTiming);
        cudaEventCreateWithFlags(&ev_join, cudaEventDisableTiming);
    }

    const size_t fused_smem = (size_t)SM_TOTAL * sizeof(float);
    cudaFuncSetAttribute(k_fused, cudaFuncAttributeMaxDynamicSharedMemorySize, (int)fused_smem);

    // fork: k_ab runs concurrently with the CSR build chain
    cudaEventRecord(ev_fork, 0);
    cudaStreamWaitEvent(s_ab, ev_fork, 0);
    dim3 abg(7, 313);
    k_ab<<<abg, 256, 0, s_ab>>>(x, Wpre, bpre);
    cudaEventRecord(ev_join, s_ab);

    k_zero<<<(N_NODES + 255) / 256, 256>>>();
    k_count<<<(N_EDGES + 255) / 256, 256>>>(dst);
    k_offsets<<<(N_NODES + 255) / 256, 256>>>();
    k_fill<<<(N_EDGES + 255) / 256, 256>>>(src, dst);
    k_sort<<<(N_NODES + 7) / 8, 256>>>();

    // join: k_fused needs both the CSR chain (default stream order) and k_ab
    cudaStreamWaitEvent(0, ev_join, 0);
    k_fused<<<POST_BLOCKS, FUSED_T, fused_smem>>>(x, Wpost, bpost, Wlin, blin, avg);
    k_norm<<<EMB, 256>>>(gnw, gnb, gms);
    k_head<<<(N_NODES + 7) / 8, 256>>>(W1, b1, W2, b2, out);
}